// round 3
// baseline (speedup 1.0000x reference)
#include <cuda_runtime.h>
#include <cuda_bf16.h>
#include <cstdint>

#define ROWS_TOT 65536
#define KPAD1    1312       // 1283 padded to 41*32
#define ITERS1   41
#define K2       256
#define ITERS2   8
#define INV_CAT  (1.0f/1283.0f)

// ---------------- scratch (no cudaMalloc allowed) ----------------
__device__ __align__(16) uint32_t      g_y1[ROWS_TOT * 256];   // packed bf16 hi | lo<<16
__device__ __align__(16) __nv_bfloat16 g_B1hi[KPAD1 * 256];
__device__ __align__(16) __nv_bfloat16 g_B1lo[KPAD1 * 256];
__device__ __align__(16) __nv_bfloat16 g_B2hi[256 * 256];
__device__ __align__(16) __nv_bfloat16 g_B2lo[256 * 256];
__device__ float g_v[256];
__device__ float g_u[256];

// ---------------- helpers ----------------
__device__ __forceinline__ uint32_t smem_u32(const void* p) {
    uint32_t a;
    asm("{ .reg .u64 t; cvta.to.shared.u64 t, %1; cvt.u32.u64 %0, t; }" : "=r"(a) : "l"(p));
    return a;
}
__device__ __forceinline__ void ldsm_x4(uint32_t* f, uint32_t a) {
    asm volatile("ldmatrix.sync.aligned.m8n8.x4.shared.b16 {%0,%1,%2,%3}, [%4];"
                 : "=r"(f[0]), "=r"(f[1]), "=r"(f[2]), "=r"(f[3]) : "r"(a));
}
__device__ __forceinline__ void ldsm_x4t(uint32_t* f, uint32_t a) {
    asm volatile("ldmatrix.sync.aligned.m8n8.x4.trans.shared.b16 {%0,%1,%2,%3}, [%4];"
                 : "=r"(f[0]), "=r"(f[1]), "=r"(f[2]), "=r"(f[3]) : "r"(a));
}
__device__ __forceinline__ void mma16816(float* c, const uint32_t* a, uint32_t b0, uint32_t b1) {
    asm volatile("mma.sync.aligned.m16n8k16.row.col.f32.bf16.bf16.f32 "
                 "{%0,%1,%2,%3}, {%4,%5,%6,%7}, {%8,%9}, {%0,%1,%2,%3};"
                 : "+f"(c[0]), "+f"(c[1]), "+f"(c[2]), "+f"(c[3])
                 : "r"(a[0]), "r"(a[1]), "r"(a[2]), "r"(a[3]), "r"(b0), "r"(b1));
}
__device__ __forceinline__ float gelu_f(float x) {
    return 0.5f * x * (1.0f + erff(x * 0.70710678118654752f));
}
__device__ __forceinline__ uint32_t pack_hl(float x) {
    __nv_bfloat16 h = __float2bfloat16(x);
    __nv_bfloat16 l = __float2bfloat16(x - __bfloat162float(h));
    return (uint32_t)__bfloat16_as_ushort(h) | ((uint32_t)__bfloat16_as_ushort(l) << 16);
}
__device__ __forceinline__ void split2(float x0, float x1, uint32_t& hp, uint32_t& lp) {
    __nv_bfloat16 h0 = __float2bfloat16(x0), h1 = __float2bfloat16(x1);
    float r0 = x0 - __bfloat162float(h0), r1 = x1 - __bfloat162float(h1);
    __nv_bfloat16 l0 = __float2bfloat16(r0), l1 = __float2bfloat16(r1);
    hp = (uint32_t)__bfloat16_as_ushort(h0) | ((uint32_t)__bfloat16_as_ushort(h1) << 16);
    lp = (uint32_t)__bfloat16_as_ushort(l0) | ((uint32_t)__bfloat16_as_ushort(l1) << 16);
}

// shared mma core: A tiles stride 40 halves, B tiles stride 136 halves
__device__ __forceinline__ void mma_chunk(float (&acc)[2][8][4],
                                          uint32_t aHiB, uint32_t aLoB,
                                          uint32_t bHiB, uint32_t bLoB,
                                          int m0w, int n0w, int lr, int lc) {
#pragma unroll
    for (int kk = 0; kk < 32; kk += 16) {
        uint32_t ah[2][4], al[2][4];
#pragma unroll
        for (int mi = 0; mi < 2; mi++) {
            uint32_t off = (uint32_t)(((m0w + mi * 16 + lr) * 40 + kk + lc) * 2);
            ldsm_x4(ah[mi], aHiB + off);
            ldsm_x4(al[mi], aLoB + off);
        }
#pragma unroll
        for (int np = 0; np < 4; np++) {
            uint32_t boff = (uint32_t)(((kk + lr) * 136 + n0w + np * 16 + lc) * 2);
            uint32_t bh[4], bl[4];
            ldsm_x4t(bh, bHiB + boff);
            ldsm_x4t(bl, bLoB + boff);
#pragma unroll
            for (int mi = 0; mi < 2; mi++) {
                mma16816(acc[mi][np * 2],     ah[mi], bh[0], bh[1]);
                mma16816(acc[mi][np * 2 + 1], ah[mi], bh[2], bh[3]);
                mma16816(acc[mi][np * 2],     ah[mi], bl[0], bl[1]);
                mma16816(acc[mi][np * 2 + 1], ah[mi], bl[2], bl[3]);
                mma16816(acc[mi][np * 2],     al[mi], bh[0], bh[1]);
                mma16816(acc[mi][np * 2 + 1], al[mi], bh[2], bh[3]);
            }
        }
    }
}

__device__ __forceinline__ void stage_B(__nv_bfloat16* Bs, const __nv_bfloat16* Bg, int t) {
    int row = t >> 3, colh = (t & 7) * 16;
    const uint4* src = (const uint4*)(Bg + row * 256 + colh);
    uint4 v0 = src[0], v1 = src[1];
    uint4* dst = (uint4*)(Bs + row * 136 + colh);
    dst[0] = v0; dst[1] = v1;
}

// ---------------- prep kernels ----------------
__global__ void prep_w1(const float* __restrict__ W1, const float* __restrict__ gamma) {
    int c = blockIdx.x, d = threadIdx.x;
    float w = (c < 1283) ? W1[c * 256 + d] * gamma[c] : 0.0f;
    __nv_bfloat16 h = __float2bfloat16(w);
    __nv_bfloat16 l = __float2bfloat16(w - __bfloat162float(h));
    g_B1hi[c * 256 + d] = h;
    g_B1lo[c * 256 + d] = l;
}
__global__ void prep_w2(const float* __restrict__ W2) {
    int c = blockIdx.x, d = threadIdx.x;
    float w = W2[c * 256 + d];
    __nv_bfloat16 h = __float2bfloat16(w);
    __nv_bfloat16 l = __float2bfloat16(w - __bfloat162float(h));
    g_B2hi[c * 256 + d] = h;
    g_B2lo[c * 256 + d] = l;
}
__global__ void prep_vu(const float* __restrict__ W1, const float* __restrict__ gamma,
                        const float* __restrict__ beta, const float* __restrict__ b1) {
    int d = threadIdx.x;
    float v = 0.f, u = 0.f;
    for (int c = 0; c < 1283; c++) {
        float w = W1[c * 256 + d];
        v += gamma[c] * w;
        u += beta[c] * w;
    }
    g_v[d] = v;
    g_u[d] = u + b1[d];
}

// ---------------- GEMM1: raw-x @ W1g, LN-folded epilogue + GELU, pack to g_y1 ----------------
__global__ __launch_bounds__(256) void gemm1(
    const float* __restrict__ pt, const float* __restrict__ sh,
    const float* __restrict__ dyn, const float* __restrict__ sem,
    const float* __restrict__ pit, const float* __restrict__ rel,
    const float* __restrict__ vis) {
    __shared__ __nv_bfloat16 Ahi[128 * 40], Alo[128 * 40];
    __shared__ __nv_bfloat16 Bhi[32 * 136], Blo[32 * 136];
    __shared__ float s_sum[128], s_ss[128];

    int t = threadIdx.x, l = t & 31, wid = t >> 5;
    int m0w = (wid & 3) * 32, n0w = (wid >> 2) * 64;
    int lr = l & 15, lc = (l & 16) >> 1;
    int rowBase = blockIdx.x * 128, d0 = blockIdx.y * 128;

    float acc[2][8][4];
#pragma unroll
    for (int i = 0; i < 2; i++)
#pragma unroll
        for (int j = 0; j < 8; j++)
#pragma unroll
            for (int k = 0; k < 4; k++) acc[i][j][k] = 0.f;
    float sum = 0.f, ss = 0.f;

    uint32_t aHiB = smem_u32(Ahi), aLoB = smem_u32(Alo);
    uint32_t bHiB = smem_u32(Bhi), bLoB = smem_u32(Blo);

    int r = rowBase + (t >> 1);
    int b_ = r >> 14, m_ = (r >> 6) & 255, h_ = r & 63;
    const float* base0 = pt + ((b_ << 8) + m_) * 256;
    const float* base1 = sh + ((b_ << 6) + h_) * 256;
    const float* base2 = dyn + (size_t)r * 256;
    const float* base3 = sem + (size_t)r * 256;
    const float* base4 = pit + (size_t)r * 256;

    for (int it = 0; it < ITERS1; ++it) {
        // ---- stage A (gather concat, hi/lo split, stats) ----
        int c0 = it * 32 + (t & 1) * 16;
        float x[16];
        if (c0 < 1280) {
            int seg = c0 >> 8, off = c0 & 255;
            const float* p = (seg == 0) ? base0 : (seg == 1) ? base1
                           : (seg == 2) ? base2 : (seg == 3) ? base3 : base4;
            p += off;
#pragma unroll
            for (int j = 0; j < 4; j++) {
                float4 f = ((const float4*)p)[j];
                x[4 * j] = f.x; x[4 * j + 1] = f.y; x[4 * j + 2] = f.z; x[4 * j + 3] = f.w;
            }
        } else {
#pragma unroll
            for (int j = 0; j < 16; j++) {
                int c = c0 + j;
                x[j] = (c < 1282) ? rel[(size_t)r * 2 + (c - 1280)]
                     : (c == 1282) ? vis[r] : 0.f;
            }
        }
        uint32_t hp[8], lp[8];
#pragma unroll
        for (int j = 0; j < 8; j++) {
            float x0 = x[2 * j], x1 = x[2 * j + 1];
            sum += x0 + x1;
            ss += x0 * x0 + x1 * x1;
            split2(x0, x1, hp[j], lp[j]);
        }
        {
            __nv_bfloat16* da = Ahi + (t >> 1) * 40 + (t & 1) * 16;
            __nv_bfloat16* dl = Alo + (t >> 1) * 40 + (t & 1) * 16;
            uint4 v0 = make_uint4(hp[0], hp[1], hp[2], hp[3]);
            uint4 v1 = make_uint4(hp[4], hp[5], hp[6], hp[7]);
            ((uint4*)da)[0] = v0; ((uint4*)da)[1] = v1;
            uint4 w0 = make_uint4(lp[0], lp[1], lp[2], lp[3]);
            uint4 w1 = make_uint4(lp[4], lp[5], lp[6], lp[7]);
            ((uint4*)dl)[0] = w0; ((uint4*)dl)[1] = w1;
        }
        // ---- stage B ----
        stage_B(Bhi, g_B1hi + (size_t)it * 32 * 256 + d0, t);
        stage_B(Blo, g_B1lo + (size_t)it * 32 * 256 + d0, t);
        __syncthreads();
        mma_chunk(acc, aHiB, aLoB, bHiB, bLoB, m0w, n0w, lr, lc);
        __syncthreads();
    }

    // ---- row stats ----
    sum += __shfl_xor_sync(0xffffffffu, sum, 1);
    ss  += __shfl_xor_sync(0xffffffffu, ss, 1);
    if (!(t & 1)) { s_sum[t >> 1] = sum; s_ss[t >> 1] = ss; }
    __syncthreads();

    // ---- epilogue: LN correction + GELU + pack ----
    int rq = l >> 2, cq = (l & 3) * 2;
#pragma unroll
    for (int mi = 0; mi < 2; mi++) {
        int rl = m0w + mi * 16 + rq;
        float mu0 = s_sum[rl] * INV_CAT;
        float rs0 = rsqrtf(s_ss[rl] * INV_CAT - mu0 * mu0 + 1e-5f);
        float mu1 = s_sum[rl + 8] * INV_CAT;
        float rs1 = rsqrtf(s_ss[rl + 8] * INV_CAT - mu1 * mu1 + 1e-5f);
        int grow = rowBase + rl;
#pragma unroll
        for (int ni = 0; ni < 8; ni++) {
            int gcol = d0 + n0w + ni * 8 + cq;
            float v0 = g_v[gcol], v1 = g_v[gcol + 1];
            float u0 = g_u[gcol], u1 = g_u[gcol + 1];
            float* a = acc[mi][ni];
            float y0 = gelu_f(rs0 * (a[0] - mu0 * v0) + u0);
            float y1 = gelu_f(rs0 * (a[1] - mu0 * v1) + u1);
            float y2 = gelu_f(rs1 * (a[2] - mu1 * v0) + u0);
            float y3 = gelu_f(rs1 * (a[3] - mu1 * v1) + u1);
            uint2 p0 = make_uint2(pack_hl(y0), pack_hl(y1));
            uint2 p1 = make_uint2(pack_hl(y2), pack_hl(y3));
            *(uint2*)&g_y1[(size_t)grow * 256 + gcol] = p0;
            *(uint2*)&g_y1[(size_t)(grow + 8) * 256 + gcol] = p1;
        }
    }
}

// ---------------- GEMM2: y1 @ W2 + b2, GELU -> out ----------------
__global__ __launch_bounds__(256) void gemm2(const float* __restrict__ b2,
                                             float* __restrict__ out) {
    __shared__ __nv_bfloat16 Ahi[128 * 40], Alo[128 * 40];
    __shared__ __nv_bfloat16 Bhi[32 * 136], Blo[32 * 136];

    int t = threadIdx.x, l = t & 31, wid = t >> 5;
    int m0w = (wid & 3) * 32, n0w = (wid >> 2) * 64;
    int lr = l & 15, lc = (l & 16) >> 1;
    int rowBase = blockIdx.x * 128, d0 = blockIdx.y * 128;

    float acc[2][8][4];
#pragma unroll
    for (int i = 0; i < 2; i++)
#pragma unroll
        for (int j = 0; j < 8; j++)
#pragma unroll
            for (int k = 0; k < 4; k++) acc[i][j][k] = 0.f;

    uint32_t aHiB = smem_u32(Ahi), aLoB = smem_u32(Alo);
    uint32_t bHiB = smem_u32(Bhi), bLoB = smem_u32(Blo);
    int r = rowBase + (t >> 1);

    for (int it = 0; it < ITERS2; ++it) {
        int c0 = it * 32 + (t & 1) * 16;
        const uint32_t* p = g_y1 + (size_t)r * 256 + c0;
        uint32_t hp[8], lp[8];
#pragma unroll
        for (int j = 0; j < 4; j++) {
            uint4 q = ((const uint4*)p)[j];
            hp[2 * j]     = (q.x & 0xffffu) | ((q.y & 0xffffu) << 16);
            hp[2 * j + 1] = (q.z & 0xffffu) | ((q.w & 0xffffu) << 16);
            lp[2 * j]     = (q.x >> 16) | (q.y & 0xffff0000u);
            lp[2 * j + 1] = (q.z >> 16) | (q.w & 0xffff0000u);
        }
        {
            __nv_bfloat16* da = Ahi + (t >> 1) * 40 + (t & 1) * 16;
            __nv_bfloat16* dl = Alo + (t >> 1) * 40 + (t & 1) * 16;
            uint4 v0 = make_uint4(hp[0], hp[1], hp[2], hp[3]);
            uint4 v1 = make_uint4(hp[4], hp[5], hp[6], hp[7]);
            ((uint4*)da)[0] = v0; ((uint4*)da)[1] = v1;
            uint4 w0 = make_uint4(lp[0], lp[1], lp[2], lp[3]);
            uint4 w1 = make_uint4(lp[4], lp[5], lp[6], lp[7]);
            ((uint4*)dl)[0] = w0; ((uint4*)dl)[1] = w1;
        }
        stage_B(Bhi, g_B2hi + (size_t)it * 32 * 256 + d0, t);
        stage_B(Blo, g_B2lo + (size_t)it * 32 * 256 + d0, t);
        __syncthreads();
        mma_chunk(acc, aHiB, aLoB, bHiB, bLoB, m0w, n0w, lr, lc);
        __syncthreads();
    }

    int rq = l >> 2, cq = (l & 3) * 2;
#pragma unroll
    for (int mi = 0; mi < 2; mi++) {
        int rl = m0w + mi * 16 + rq;
        int grow = rowBase + rl;
#pragma unroll
        for (int ni = 0; ni < 8; ni++) {
            int gcol = d0 + n0w + ni * 8 + cq;
            float u0 = b2[gcol], u1 = b2[gcol + 1];
            float* a = acc[mi][ni];
            float2 q0 = make_float2(gelu_f(a[0] + u0), gelu_f(a[1] + u1));
            float2 q1 = make_float2(gelu_f(a[2] + u0), gelu_f(a[3] + u1));
            *(float2*)&out[(size_t)grow * 256 + gcol] = q0;
            *(float2*)&out[(size_t)(grow + 8) * 256 + gcol] = q1;
        }
    }
}

// ---------------- launch ----------------
extern "C" void kernel_launch(void* const* d_in, const int* in_sizes, int n_in,
                              void* d_out, int out_size) {
    const float* pt    = (const float*)d_in[0];
    const float* sh    = (const float*)d_in[1];
    const float* dyn   = (const float*)d_in[2];
    const float* sem   = (const float*)d_in[3];
    const float* pit   = (const float*)d_in[4];
    const float* rel   = (const float*)d_in[5];
    const float* vis   = (const float*)d_in[6];
    const float* gamma = (const float*)d_in[7];
    const float* beta  = (const float*)d_in[8];
    const float* W1    = (const float*)d_in[9];
    const float* b1    = (const float*)d_in[10];
    const float* W2    = (const float*)d_in[11];
    const float* b2    = (const float*)d_in[12];
    float* out = (float*)d_out;

    prep_w1<<<KPAD1, 256>>>(W1, gamma);
    prep_w2<<<256, 256>>>(W2);
    prep_vu<<<1, 256>>>(W1, gamma, beta, b1);
    gemm1<<<dim3(512, 2), 256>>>(pt, sh, dyn, sem, pit, rel, vis);
    gemm2<<<dim3(512, 2), 256>>>(b2, out);
}

// round 5
// speedup vs baseline: 1.2552x; 1.2552x over previous
#include <cuda_runtime.h>
#include <cuda_bf16.h>
#include <cstdint>

#define NCH1 41                 // K1 = 1283 -> 41 chunks of 32
#define NCH2 8                  // K2 = 256  -> 8 chunks of 32
#define KPAD1 1312
#define INV_CAT (1.0f/1283.0f)

// smem layout (bytes, within dynamic smem):
//   A stage s: hi at s*20480, lo at s*20480+10240   (128 rows x 40 halves)
//   B stage s: hi at 40960+s*17408, lo at +8704     (32 rows x 136 halves)
#define A_ST   20480
#define B_BASE 40960
#define B_ST   17408
#define SMEM_DYN (B_BASE + 2*B_ST)   // 75776

// ---------------- scratch (no cudaMalloc allowed) ----------------
__device__ __align__(16) uint32_t      g_y1[65536u*256];   // packed bf16 hi | lo<<16
__device__ __align__(16) __nv_bfloat16 g_B1hi[KPAD1*256];
__device__ __align__(16) __nv_bfloat16 g_B1lo[KPAD1*256];
__device__ __align__(16) __nv_bfloat16 g_B2hi[256*256];
__device__ __align__(16) __nv_bfloat16 g_B2lo[256*256];
__device__ float g_v[256];
__device__ float g_u[256];

// ---------------- helpers ----------------
__device__ __forceinline__ uint32_t smem_u32(const void* p) {
    uint32_t a;
    asm("{ .reg .u64 t; cvta.to.shared.u64 t, %1; cvt.u32.u64 %0, t; }" : "=r"(a) : "l"(p));
    return a;
}
#define CP_A16(dst, src) \
    asm volatile("cp.async.cg.shared.global [%0], [%1], 16;" :: "r"(dst), "l"(src) : "memory")
#define CP_COMMIT() asm volatile("cp.async.commit_group;" ::: "memory")
#define CP_WAIT0()  asm volatile("cp.async.wait_group 0;" ::: "memory")

__device__ __forceinline__ void ldsm_x4(uint32_t* f, uint32_t a) {
    asm volatile("ldmatrix.sync.aligned.m8n8.x4.shared.b16 {%0,%1,%2,%3}, [%4];"
                 : "=r"(f[0]), "=r"(f[1]), "=r"(f[2]), "=r"(f[3]) : "r"(a));
}
__device__ __forceinline__ void ldsm_x4t(uint32_t* f, uint32_t a) {
    asm volatile("ldmatrix.sync.aligned.m8n8.x4.trans.shared.b16 {%0,%1,%2,%3}, [%4];"
                 : "=r"(f[0]), "=r"(f[1]), "=r"(f[2]), "=r"(f[3]) : "r"(a));
}
__device__ __forceinline__ void mma16816(float* c, const uint32_t* a, uint32_t b0, uint32_t b1) {
    asm volatile("mma.sync.aligned.m16n8k16.row.col.f32.bf16.bf16.f32 "
                 "{%0,%1,%2,%3}, {%4,%5,%6,%7}, {%8,%9}, {%0,%1,%2,%3};"
                 : "+f"(c[0]), "+f"(c[1]), "+f"(c[2]), "+f"(c[3])
                 : "r"(a[0]), "r"(a[1]), "r"(a[2]), "r"(a[3]), "r"(b0), "r"(b1));
}
__device__ __forceinline__ float gelu_f(float x) {
    return 0.5f * x * (1.0f + erff(x * 0.70710678118654752f));
}
__device__ __forceinline__ uint32_t pack_hl(float x) {
    __nv_bfloat16 h = __float2bfloat16(x);
    __nv_bfloat16 l = __float2bfloat16(x - __bfloat162float(h));
    return (uint32_t)__bfloat16_as_ushort(h) | ((uint32_t)__bfloat16_as_ushort(l) << 16);
}
__device__ __forceinline__ void split2(float x0, float x1, uint32_t& hp, uint32_t& lp) {
    __nv_bfloat16 h0 = __float2bfloat16(x0), h1 = __float2bfloat16(x1);
    float r0 = x0 - __bfloat162float(h0), r1 = x1 - __bfloat162float(h1);
    __nv_bfloat16 l0 = __float2bfloat16(r0), l1 = __float2bfloat16(r1);
    hp = (uint32_t)__bfloat16_as_ushort(h0) | ((uint32_t)__bfloat16_as_ushort(h1) << 16);
    lp = (uint32_t)__bfloat16_as_ushort(l0) | ((uint32_t)__bfloat16_as_ushort(l1) << 16);
}

// mma core: A tiles stride 40 halves, B tiles stride 136 halves (one stage)
__device__ __forceinline__ void mma_chunk(float (&acc)[2][8][4],
                                          uint32_t aHiB, uint32_t aLoB,
                                          uint32_t bHiB, uint32_t bLoB,
                                          int m0w, int n0w, int lr, int lc) {
#pragma unroll
    for (int kk = 0; kk < 32; kk += 16) {
        uint32_t ah[2][4], al[2][4];
#pragma unroll
        for (int mi = 0; mi < 2; mi++) {
            uint32_t off = (uint32_t)(((m0w + mi * 16 + lr) * 40 + kk + lc) * 2);
            ldsm_x4(ah[mi], aHiB + off);
            ldsm_x4(al[mi], aLoB + off);
        }
#pragma unroll
        for (int np = 0; np < 4; np++) {
            uint32_t boff = (uint32_t)(((kk + lr) * 136 + n0w + np * 16 + lc) * 2);
            uint32_t bh[4], bl[4];
            ldsm_x4t(bh, bHiB + boff);
            ldsm_x4t(bl, bLoB + boff);
#pragma unroll
            for (int mi = 0; mi < 2; mi++) {
                mma16816(acc[mi][np * 2],     ah[mi], bh[0], bh[1]);
                mma16816(acc[mi][np * 2 + 1], ah[mi], bh[2], bh[3]);
                mma16816(acc[mi][np * 2],     ah[mi], bl[0], bl[1]);
                mma16816(acc[mi][np * 2 + 1], ah[mi], bl[2], bl[3]);
                mma16816(acc[mi][np * 2],     al[mi], bh[0], bh[1]);
                mma16816(acc[mi][np * 2 + 1], al[mi], bh[2], bh[3]);
            }
        }
    }
}

// async-copy one B stage (hi+lo) for chunk c; srcHi/srcLo already offset to chunk+d0
__device__ __forceinline__ void cpB(uint32_t smBase, int s,
                                    const __nv_bfloat16* srcHi,
                                    const __nv_bfloat16* srcLo, int t) {
    int row = t >> 3, colh = (t & 7) * 16;
    uint32_t d = smBase + B_BASE + s * B_ST + (uint32_t)(row * 136 + colh) * 2;
    const char* sH = (const char*)(srcHi + row * 256 + colh);
    const char* sL = (const char*)(srcLo + row * 256 + colh);
    CP_A16(d, sH);            CP_A16(d + 16, sH + 16);
    CP_A16(d + 8704, sL);     CP_A16(d + 8704 + 16, sL + 16);
}

// store 16 cols (as 8 hi + 8 lo packed pairs) into A stage s
__device__ __forceinline__ void stageA_store(char* sm, int s, int row, int half,
                                             const uint32_t* hp, const uint32_t* lp) {
    char* da = sm + s * A_ST + (uint32_t)(row * 40 + half * 16) * 2;
    char* dl = da + 10240;
    ((uint4*)da)[0] = make_uint4(hp[0], hp[1], hp[2], hp[3]);
    ((uint4*)da)[1] = make_uint4(hp[4], hp[5], hp[6], hp[7]);
    ((uint4*)dl)[0] = make_uint4(lp[0], lp[1], lp[2], lp[3]);
    ((uint4*)dl)[1] = make_uint4(lp[4], lp[5], lp[6], lp[7]);
}

__device__ __forceinline__ void load_x16(const float* const* seg,
                                         const float* rel, const float* vis,
                                         int r, int c, int half, float* x) {
    int c0 = c * 32 + half * 16;
    if (c0 < 1280) {
        const float* p = seg[c0 >> 8] + (c0 & 255);
#pragma unroll
        for (int j = 0; j < 4; j++) {
            float4 f = ((const float4*)p)[j];
            x[4 * j] = f.x; x[4 * j + 1] = f.y; x[4 * j + 2] = f.z; x[4 * j + 3] = f.w;
        }
    } else {
#pragma unroll
        for (int j = 0; j < 16; j++) {
            int cc = c0 + j;
            x[j] = (cc < 1282) ? rel[(size_t)r * 2 + (cc - 1280)]
                 : (cc == 1282) ? vis[r] : 0.f;
        }
    }
}

// ---------------- prep kernels ----------------
__global__ void prep_w1(const float* __restrict__ W1, const float* __restrict__ gamma) {
    int c = blockIdx.x, d = threadIdx.x;
    float w = (c < 1283) ? W1[(size_t)c * 256 + d] * gamma[c] : 0.0f;
    __nv_bfloat16 h = __float2bfloat16(w);
    __nv_bfloat16 l = __float2bfloat16(w - __bfloat162float(h));
    g_B1hi[(size_t)c * 256 + d] = h;
    g_B1lo[(size_t)c * 256 + d] = l;
}
__global__ void prep_w2(const float* __restrict__ W2) {
    int c = blockIdx.x, d = threadIdx.x;
    float w = W2[(size_t)c * 256 + d];
    __nv_bfloat16 h = __float2bfloat16(w);
    __nv_bfloat16 l = __float2bfloat16(w - __bfloat162float(h));
    g_B2hi[(size_t)c * 256 + d] = h;
    g_B2lo[(size_t)c * 256 + d] = l;
}
__global__ void prep_vu(const float* __restrict__ W1, const float* __restrict__ gamma,
                        const float* __restrict__ beta, const float* __restrict__ b1) {
    int d = threadIdx.x;
    float v = 0.f, u = 0.f;
    for (int c = 0; c < 1283; c++) {
        float w = W1[(size_t)c * 256 + d];
        v += gamma[c] * w;
        u += beta[c] * w;
    }
    g_v[d] = v;
    g_u[d] = u + b1[d];
}

// ---------------- GEMM1: raw concat-x @ W1g, LN-folded epilogue + GELU -> g_y1 ----------------
__global__ __launch_bounds__(256) void gemm1(
    const float* __restrict__ pt, const float* __restrict__ sh,
    const float* __restrict__ dyn, const float* __restrict__ sem,
    const float* __restrict__ pit, const float* __restrict__ rel,
    const float* __restrict__ vis) {
    extern __shared__ char sm[];
    __shared__ float s_sum[128], s_ss[128];

    int t = threadIdx.x, l = t & 31, wid = t >> 5;
    int m0w = (wid & 3) * 32, n0w = (wid >> 2) * 64;
    int lr = l & 15, lc = (l & 16) >> 1;
    int rowBase = blockIdx.x * 128, d0 = blockIdx.y * 128;
    int half = t & 1, row = t >> 1;
    int r = rowBase + row;
    int b_ = r >> 14, m_ = (r >> 6) & 255, h_ = r & 63;
    const float* seg[5] = { pt + (size_t)((b_ << 8) + m_) * 256,
                            sh + (size_t)((b_ << 6) + h_) * 256,
                            dyn + (size_t)r * 256,
                            sem + (size_t)r * 256,
                            pit + (size_t)r * 256 };
    uint32_t base = smem_u32(sm);

    float acc[2][8][4];
#pragma unroll
    for (int i = 0; i < 2; i++)
#pragma unroll
        for (int j = 0; j < 8; j++)
#pragma unroll
            for (int k = 0; k < 4; k++) acc[i][j][k] = 0.f;
    float sum = 0.f, ss = 0.f;

    float x[16];
    uint32_t hp[8], lp[8];

    // ---- prologue: stage chunk 0 ----
    load_x16(seg, rel, vis, r, 0, half, x);
    cpB(base, 0, g_B1hi + d0, g_B1lo + d0, t);
    CP_COMMIT();
#pragma unroll
    for (int j = 0; j < 8; j++) {
        float a = x[2 * j], b = x[2 * j + 1];
        sum += a + b; ss = fmaf(a, a, ss); ss = fmaf(b, b, ss);
        split2(a, b, hp[j], lp[j]);
    }
    stageA_store(sm, 0, row, half, hp, lp);
    CP_WAIT0();
    __syncthreads();

    for (int c = 0; c < NCH1; c++) {
        int s = c & 1, ns = s ^ 1;
        bool more = (c + 1 < NCH1);
        if (more) {
            load_x16(seg, rel, vis, r, c + 1, half, x);   // LDG in flight over the MMAs
            cpB(base, ns, g_B1hi + (size_t)(c + 1) * 8192 + d0,
                           g_B1lo + (size_t)(c + 1) * 8192 + d0, t);
            CP_COMMIT();
        }
        mma_chunk(acc, base + s * A_ST, base + s * A_ST + 10240,
                       base + B_BASE + s * B_ST, base + B_BASE + s * B_ST + 8704,
                  m0w, n0w, lr, lc);
        if (more) {
#pragma unroll
            for (int j = 0; j < 8; j++) {
                float a = x[2 * j], b = x[2 * j + 1];
                sum += a + b; ss = fmaf(a, a, ss); ss = fmaf(b, b, ss);
                split2(a, b, hp[j], lp[j]);
            }
            stageA_store(sm, ns, row, half, hp, lp);
        }
        CP_WAIT0();
        __syncthreads();
    }

    // ---- row stats ----
    sum += __shfl_xor_sync(0xffffffffu, sum, 1);
    ss  += __shfl_xor_sync(0xffffffffu, ss, 1);
    if (!half) { s_sum[row] = sum; s_ss[row] = ss; }
    __syncthreads();

    // ---- epilogue: LN correction + GELU + pack ----
    int rq = l >> 2, cq = (l & 3) * 2;
#pragma unroll
    for (int mi = 0; mi < 2; mi++) {
        int rl = m0w + mi * 16 + rq;
        float mu0 = s_sum[rl] * INV_CAT;
        float rs0 = rsqrtf(fmaf(-mu0, mu0, s_ss[rl] * INV_CAT) + 1e-5f);
        float mu1 = s_sum[rl + 8] * INV_CAT;
        float rs1 = rsqrtf(fmaf(-mu1, mu1, s_ss[rl + 8] * INV_CAT) + 1e-5f);
        int grow = rowBase + rl;
#pragma unroll
        for (int ni = 0; ni < 8; ni++) {
            int gcol = d0 + n0w + ni * 8 + cq;
            float v0 = g_v[gcol], v1 = g_v[gcol + 1];
            float u0 = g_u[gcol], u1 = g_u[gcol + 1];
            float* a = acc[mi][ni];
            float y0 = gelu_f(fmaf(rs0, a[0] - mu0 * v0, u0));
            float y1 = gelu_f(fmaf(rs0, a[1] - mu0 * v1, u1));
            float y2 = gelu_f(fmaf(rs1, a[2] - mu1 * v0, u0));
            float y3 = gelu_f(fmaf(rs1, a[3] - mu1 * v1, u1));
            *(uint2*)&g_y1[(size_t)grow * 256 + gcol] = make_uint2(pack_hl(y0), pack_hl(y1));
            *(uint2*)&g_y1[(size_t)(grow + 8) * 256 + gcol] = make_uint2(pack_hl(y2), pack_hl(y3));
        }
    }
}

// ---------------- GEMM2: y1 @ W2 + b2, GELU -> out ----------------
__global__ __launch_bounds__(256) void gemm2(const float* __restrict__ b2,
                                             float* __restrict__ out) {
    extern __shared__ char sm[];
    int t = threadIdx.x, l = t & 31, wid = t >> 5;
    int m0w = (wid & 3) * 32, n0w = (wid >> 2) * 64;
    int lr = l & 15, lc = (l & 16) >> 1;
    int rowBase = blockIdx.x * 128, d0 = blockIdx.y * 128;
    int half = t & 1, row = t >> 1;
    int r = rowBase + row;
    uint32_t base = smem_u32(sm);

    float acc[2][8][4];
#pragma unroll
    for (int i = 0; i < 2; i++)
#pragma unroll
        for (int j = 0; j < 8; j++)
#pragma unroll
            for (int k = 0; k < 4; k++) acc[i][j][k] = 0.f;

    uint4 q[4];
    uint32_t hp[8], lp[8];
    const uint32_t* ybase = g_y1 + (size_t)r * 256 + half * 16;

    // prologue
#pragma unroll
    for (int j = 0; j < 4; j++) q[j] = ((const uint4*)ybase)[j];
    cpB(base, 0, g_B2hi + d0, g_B2lo + d0, t);
    CP_COMMIT();
#pragma unroll
    for (int j = 0; j < 4; j++) {
        uint4 v = q[j];
        hp[2 * j]     = (v.x & 0xffffu) | ((v.y & 0xffffu) << 16);
        hp[2 * j + 1] = (v.z & 0xffffu) | ((v.w & 0xffffu) << 16);
        lp[2 * j]     = (v.x >> 16) | (v.y & 0xffff0000u);
        lp[2 * j + 1] = (v.z >> 16) | (v.w & 0xffff0000u);
    }
    stageA_store(sm, 0, row, half, hp, lp);
    CP_WAIT0();
    __syncthreads();

    for (int c = 0; c < NCH2; c++) {
        int s = c & 1, ns = s ^ 1;
        bool more = (c + 1 < NCH2);
        if (more) {
#pragma unroll
            for (int j = 0; j < 4; j++) q[j] = ((const uint4*)(ybase + (c + 1) * 32))[j];
            cpB(base, ns, g_B2hi + (size_t)(c + 1) * 8192 + d0,
                           g_B2lo + (size_t)(c + 1) * 8192 + d0, t);
            CP_COMMIT();
        }
        mma_chunk(acc, base + s * A_ST, base + s * A_ST + 10240,
                       base + B_BASE + s * B_ST, base + B_BASE + s * B_ST + 8704,
                  m0w, n0w, lr, lc);
        if (more) {
#pragma unroll
            for (int j = 0; j < 4; j++) {
                uint4 v = q[j];
                hp[2 * j]     = (v.x & 0xffffu) | ((v.y & 0xffffu) << 16);
                hp[2 * j + 1] = (v.z & 0xffffu) | ((v.w & 0xffffu) << 16);
                lp[2 * j]     = (v.x >> 16) | (v.y & 0xffff0000u);
                lp[2 * j + 1] = (v.z >> 16) | (v.w & 0xffff0000u);
            }
            stageA_store(sm, ns, row, half, hp, lp);
        }
        CP_WAIT0();
        __syncthreads();
    }

    int rq = l >> 2, cq = (l & 3) * 2;
#pragma unroll
    for (int mi = 0; mi < 2; mi++) {
        int rl = m0w + mi * 16 + rq;
        int grow = rowBase + rl;
#pragma unroll
        for (int ni = 0; ni < 8; ni++) {
            int gcol = d0 + n0w + ni * 8 + cq;
            float u0 = b2[gcol], u1 = b2[gcol + 1];
            float* a = acc[mi][ni];
            *(float2*)&out[(size_t)grow * 256 + gcol] =
                make_float2(gelu_f(a[0] + u0), gelu_f(a[1] + u1));
            *(float2*)&out[(size_t)(grow + 8) * 256 + gcol] =
                make_float2(gelu_f(a[2] + u0), gelu_f(a[3] + u1));
        }
    }
}

// ---------------- launch ----------------
extern "C" void kernel_launch(void* const* d_in, const int* in_sizes, int n_in,
                              void* d_out, int out_size) {
    const float* pt    = (const float*)d_in[0];
    const float* sh    = (const float*)d_in[1];
    const float* dyn   = (const float*)d_in[2];
    const float* sem   = (const float*)d_in[3];
    const float* pit   = (const float*)d_in[4];
    const float* rel   = (const float*)d_in[5];
    const float* vis   = (const float*)d_in[6];
    const float* gamma = (const float*)d_in[7];
    const float* beta  = (const float*)d_in[8];
    const float* W1    = (const float*)d_in[9];
    const float* b1    = (const float*)d_in[10];
    const float* W2    = (const float*)d_in[11];
    const float* b2    = (const float*)d_in[12];
    float* out = (float*)d_out;

    cudaFuncSetAttribute(gemm1, cudaFuncAttributeMaxDynamicSharedMemorySize, SMEM_DYN);
    cudaFuncSetAttribute(gemm2, cudaFuncAttributeMaxDynamicSharedMemorySize, SMEM_DYN);

    prep_w1<<<KPAD1, 256>>>(W1, gamma);
    prep_w2<<<256, 256>>>(W2);
    prep_vu<<<1, 256>>>(W1, gamma, beta, b1);
    gemm1<<<dim3(512, 2), 256, SMEM_DYN>>>(pt, sh, dyn, sem, pit, rel, vis);
    gemm2<<<dim3(512, 2), 256, SMEM_DYN>>>(b2, out);
}

// round 6
// speedup vs baseline: 1.4772x; 1.1768x over previous
#include <cuda_runtime.h>
#include <cuda_bf16.h>
#include <cstdint>

#define NCH1 41                 // K1 = 1283 -> 41 chunks of 32
#define NCH2 8                  // K2 = 256  -> 8 chunks of 32
#define KPAD1 1312
#define INV_CAT (1.0f/1283.0f)

// smem layout (bytes, within dynamic smem):
//   A stage s: hi at s*20480, lo at s*20480+10240   (128 rows x 40 halves)
//   B stage s: hi at 40960+s*17408, lo at +8704     (32 rows x 136 halves)
#define A_ST   20480
#define B_BASE 40960
#define B_ST   17408
#define SMEM_DYN (B_BASE + 2*B_ST)   // 75776

// ---------------- scratch (no cudaMalloc allowed) ----------------
__device__ __align__(16) uint32_t      g_y1[65536u*256];   // packed bf16 hi | lo<<16
__device__ __align__(16) __nv_bfloat16 g_B1hi[KPAD1*256];
__device__ __align__(16) __nv_bfloat16 g_B1lo[KPAD1*256];
__device__ __align__(16) __nv_bfloat16 g_B2hi[256*256];
__device__ __align__(16) __nv_bfloat16 g_B2lo[256*256];
__device__ float g_v[256];
__device__ float g_u[256];

// ---------------- helpers ----------------
__device__ __forceinline__ uint32_t smem_u32(const void* p) {
    uint32_t a;
    asm("{ .reg .u64 t; cvta.to.shared.u64 t, %1; cvt.u32.u64 %0, t; }" : "=r"(a) : "l"(p));
    return a;
}
#define CP_A16(dst, src) \
    asm volatile("cp.async.cg.shared.global [%0], [%1], 16;" :: "r"(dst), "l"(src) : "memory")
#define CP_COMMIT() asm volatile("cp.async.commit_group;" ::: "memory")
#define CP_WAIT0()  asm volatile("cp.async.wait_group 0;" ::: "memory")

__device__ __forceinline__ void ldsm_x4(uint32_t* f, uint32_t a) {
    asm volatile("ldmatrix.sync.aligned.m8n8.x4.shared.b16 {%0,%1,%2,%3}, [%4];"
                 : "=r"(f[0]), "=r"(f[1]), "=r"(f[2]), "=r"(f[3]) : "r"(a));
}
__device__ __forceinline__ void ldsm_x4t(uint32_t* f, uint32_t a) {
    asm volatile("ldmatrix.sync.aligned.m8n8.x4.trans.shared.b16 {%0,%1,%2,%3}, [%4];"
                 : "=r"(f[0]), "=r"(f[1]), "=r"(f[2]), "=r"(f[3]) : "r"(a));
}
__device__ __forceinline__ void mma16816(float* c, const uint32_t* a, uint32_t b0, uint32_t b1) {
    asm volatile("mma.sync.aligned.m16n8k16.row.col.f32.bf16.bf16.f32 "
                 "{%0,%1,%2,%3}, {%4,%5,%6,%7}, {%8,%9}, {%0,%1,%2,%3};"
                 : "+f"(c[0]), "+f"(c[1]), "+f"(c[2]), "+f"(c[3])
                 : "r"(a[0]), "r"(a[1]), "r"(a[2]), "r"(a[3]), "r"(b0), "r"(b1));
}
__device__ __forceinline__ float gelu_f(float x) {
    return 0.5f * x * (1.0f + erff(x * 0.70710678118654752f));
}
__device__ __forceinline__ uint32_t pack_hl(float x) {
    __nv_bfloat16 h = __float2bfloat16(x);
    __nv_bfloat16 l = __float2bfloat16(x - __bfloat162float(h));
    return (uint32_t)__bfloat16_as_ushort(h) | ((uint32_t)__bfloat16_as_ushort(l) << 16);
}
__device__ __forceinline__ void split2(float x0, float x1, uint32_t& hp, uint32_t& lp) {
    __nv_bfloat16 h0 = __float2bfloat16(x0), h1 = __float2bfloat16(x1);
    float r0 = x0 - __bfloat162float(h0), r1 = x1 - __bfloat162float(h1);
    __nv_bfloat16 l0 = __float2bfloat16(r0), l1 = __float2bfloat16(r1);
    hp = (uint32_t)__bfloat16_as_ushort(h0) | ((uint32_t)__bfloat16_as_ushort(h1) << 16);
    lp = (uint32_t)__bfloat16_as_ushort(l0) | ((uint32_t)__bfloat16_as_ushort(l1) << 16);
}

// mma core, pass-major ordering: per k-step preload all fragments, then
// 3 passes of 16 independent MMAs (distinct accumulators within a pass).
__device__ __forceinline__ void mma_chunk(float (&acc)[2][8][4],
                                          uint32_t aHiB, uint32_t aLoB,
                                          uint32_t bHiB, uint32_t bLoB,
                                          int m0w, int n0w, int lr, int lc) {
#pragma unroll
    for (int kk = 0; kk < 32; kk += 16) {
        uint32_t ah[2][4], al[2][4], bh[4][4], bl[4][4];
#pragma unroll
        for (int mi = 0; mi < 2; mi++) {
            uint32_t off = (uint32_t)(((m0w + mi * 16 + lr) * 40 + kk + lc) * 2);
            ldsm_x4(ah[mi], aHiB + off);
            ldsm_x4(al[mi], aLoB + off);
        }
#pragma unroll
        for (int np = 0; np < 4; np++) {
            uint32_t boff = (uint32_t)(((kk + lr) * 136 + n0w + np * 16 + lc) * 2);
            ldsm_x4t(bh[np], bHiB + boff);
            ldsm_x4t(bl[np], bLoB + boff);
        }
        // pass 1: ah x bh  (16 MMAs, all-distinct accumulators)
#pragma unroll
        for (int np = 0; np < 4; np++)
#pragma unroll
            for (int mi = 0; mi < 2; mi++) {
                mma16816(acc[mi][np * 2],     ah[mi], bh[np][0], bh[np][1]);
                mma16816(acc[mi][np * 2 + 1], ah[mi], bh[np][2], bh[np][3]);
            }
        // pass 2: ah x bl
#pragma unroll
        for (int np = 0; np < 4; np++)
#pragma unroll
            for (int mi = 0; mi < 2; mi++) {
                mma16816(acc[mi][np * 2],     ah[mi], bl[np][0], bl[np][1]);
                mma16816(acc[mi][np * 2 + 1], ah[mi], bl[np][2], bl[np][3]);
            }
        // pass 3: al x bh
#pragma unroll
        for (int np = 0; np < 4; np++)
#pragma unroll
            for (int mi = 0; mi < 2; mi++) {
                mma16816(acc[mi][np * 2],     al[mi], bh[np][0], bh[np][1]);
                mma16816(acc[mi][np * 2 + 1], al[mi], bh[np][2], bh[np][3]);
            }
    }
}

// async-copy one B stage (hi+lo) for chunk c; srcHi/srcLo already offset to chunk+d0
__device__ __forceinline__ void cpB(uint32_t smBase, int s,
                                    const __nv_bfloat16* srcHi,
                                    const __nv_bfloat16* srcLo, int t) {
    int row = t >> 3, colh = (t & 7) * 16;
    uint32_t d = smBase + B_BASE + s * B_ST + (uint32_t)(row * 136 + colh) * 2;
    const char* sH = (const char*)(srcHi + row * 256 + colh);
    const char* sL = (const char*)(srcLo + row * 256 + colh);
    CP_A16(d, sH);            CP_A16(d + 16, sH + 16);
    CP_A16(d + 8704, sL);     CP_A16(d + 8704 + 16, sL + 16);
}

// store 16 cols (as 8 hi + 8 lo packed pairs) into A stage s
__device__ __forceinline__ void stageA_store(char* sm, int s, int row, int half,
                                             const uint32_t* hp, const uint32_t* lp) {
    char* da = sm + s * A_ST + (uint32_t)(row * 40 + half * 16) * 2;
    char* dl = da + 10240;
    ((uint4*)da)[0] = make_uint4(hp[0], hp[1], hp[2], hp[3]);
    ((uint4*)da)[1] = make_uint4(hp[4], hp[5], hp[6], hp[7]);
    ((uint4*)dl)[0] = make_uint4(lp[0], lp[1], lp[2], lp[3]);
    ((uint4*)dl)[1] = make_uint4(lp[4], lp[5], lp[6], lp[7]);
}

__device__ __forceinline__ void load_x16(const float* const* seg,
                                         const float* rel, const float* vis,
                                         int r, int c, int half, float* x) {
    int c0 = c * 32 + half * 16;
    if (c0 < 1280) {
        const float* p = seg[c0 >> 8] + (c0 & 255);
#pragma unroll
        for (int j = 0; j < 4; j++) {
            float4 f = ((const float4*)p)[j];
            x[4 * j] = f.x; x[4 * j + 1] = f.y; x[4 * j + 2] = f.z; x[4 * j + 3] = f.w;
        }
    } else {
#pragma unroll
        for (int j = 0; j < 16; j++) {
            int cc = c0 + j;
            x[j] = (cc < 1282) ? rel[(size_t)r * 2 + (cc - 1280)]
                 : (cc == 1282) ? vis[r] : 0.f;
        }
    }
}

// ---------------- prep kernels ----------------
__global__ void prep_w1(const float* __restrict__ W1, const float* __restrict__ gamma) {
    int c = blockIdx.x, d = threadIdx.x;
    float w = (c < 1283) ? W1[(size_t)c * 256 + d] * gamma[c] : 0.0f;
    __nv_bfloat16 h = __float2bfloat16(w);
    __nv_bfloat16 l = __float2bfloat16(w - __bfloat162float(h));
    g_B1hi[(size_t)c * 256 + d] = h;
    g_B1lo[(size_t)c * 256 + d] = l;
}
__global__ void prep_w2(const float* __restrict__ W2) {
    int c = blockIdx.x, d = threadIdx.x;
    float w = W2[(size_t)c * 256 + d];
    __nv_bfloat16 h = __float2bfloat16(w);
    __nv_bfloat16 l = __float2bfloat16(w - __bfloat162float(h));
    g_B2hi[(size_t)c * 256 + d] = h;
    g_B2lo[(size_t)c * 256 + d] = l;
}
__global__ void prep_vu(const float* __restrict__ W1, const float* __restrict__ gamma,
                        const float* __restrict__ beta, const float* __restrict__ b1) {
    int d = threadIdx.x;
    float v = 0.f, u = 0.f;
    for (int c = 0; c < 1283; c++) {
        float w = W1[(size_t)c * 256 + d];
        v += gamma[c] * w;
        u += beta[c] * w;
    }
    g_v[d] = v;
    g_u[d] = u + b1[d];
}

// ---------------- GEMM1: raw concat-x @ W1g, LN-folded epilogue + GELU -> g_y1 ----------------
__global__ __launch_bounds__(256) void gemm1(
    const float* __restrict__ pt, const float* __restrict__ sh,
    const float* __restrict__ dyn, const float* __restrict__ sem,
    const float* __restrict__ pit, const float* __restrict__ rel,
    const float* __restrict__ vis) {
    extern __shared__ char sm[];
    __shared__ float s_sum[128], s_ss[128];

    int t = threadIdx.x, l = t & 31, wid = t >> 5;
    int m0w = (wid & 3) * 32, n0w = (wid >> 2) * 64;
    int lr = l & 15, lc = (l & 16) >> 1;
    int rowBase = blockIdx.x * 128, d0 = blockIdx.y * 128;
    int half = t & 1, row = t >> 1;
    int r = rowBase + row;
    int b_ = r >> 14, m_ = (r >> 6) & 255, h_ = r & 63;
    const float* seg[5] = { pt + (size_t)((b_ << 8) + m_) * 256,
                            sh + (size_t)((b_ << 6) + h_) * 256,
                            dyn + (size_t)r * 256,
                            sem + (size_t)r * 256,
                            pit + (size_t)r * 256 };
    uint32_t base = smem_u32(sm);

    float acc[2][8][4];
#pragma unroll
    for (int i = 0; i < 2; i++)
#pragma unroll
        for (int j = 0; j < 8; j++)
#pragma unroll
            for (int k = 0; k < 4; k++) acc[i][j][k] = 0.f;
    float sum = 0.f, ss = 0.f;

    float x[16];
    uint32_t hp[8], lp[8];

    // ---- prologue: stage chunk 0 ----
    load_x16(seg, rel, vis, r, 0, half, x);
    cpB(base, 0, g_B1hi + d0, g_B1lo + d0, t);
    CP_COMMIT();
#pragma unroll
    for (int j = 0; j < 8; j++) {
        float a = x[2 * j], b = x[2 * j + 1];
        sum += a + b; ss = fmaf(a, a, ss); ss = fmaf(b, b, ss);
        split2(a, b, hp[j], lp[j]);
    }
    stageA_store(sm, 0, row, half, hp, lp);
    CP_WAIT0();
    __syncthreads();

    for (int c = 0; c < NCH1; c++) {
        int s = c & 1, ns = s ^ 1;
        bool more = (c + 1 < NCH1);
        if (more) {
            load_x16(seg, rel, vis, r, c + 1, half, x);   // LDG in flight over the MMAs
            cpB(base, ns, g_B1hi + (size_t)(c + 1) * 8192 + d0,
                           g_B1lo + (size_t)(c + 1) * 8192 + d0, t);
            CP_COMMIT();
        }
        mma_chunk(acc, base + s * A_ST, base + s * A_ST + 10240,
                       base + B_BASE + s * B_ST, base + B_BASE + s * B_ST + 8704,
                  m0w, n0w, lr, lc);
        if (more) {
#pragma unroll
            for (int j = 0; j < 8; j++) {
                float a = x[2 * j], b = x[2 * j + 1];
                sum += a + b; ss = fmaf(a, a, ss); ss = fmaf(b, b, ss);
                split2(a, b, hp[j], lp[j]);
            }
            stageA_store(sm, ns, row, half, hp, lp);
        }
        CP_WAIT0();
        __syncthreads();
    }

    // ---- row stats ----
    sum += __shfl_xor_sync(0xffffffffu, sum, 1);
    ss  += __shfl_xor_sync(0xffffffffu, ss, 1);
    if (!half) { s_sum[row] = sum; s_ss[row] = ss; }
    __syncthreads();

    // ---- epilogue: LN correction + GELU + pack ----
    int rq = l >> 2, cq = (l & 3) * 2;
#pragma unroll
    for (int mi = 0; mi < 2; mi++) {
        int rl = m0w + mi * 16 + rq;
        float mu0 = s_sum[rl] * INV_CAT;
        float rs0 = rsqrtf(fmaf(-mu0, mu0, s_ss[rl] * INV_CAT) + 1e-5f);
        float mu1 = s_sum[rl + 8] * INV_CAT;
        float rs1 = rsqrtf(fmaf(-mu1, mu1, s_ss[rl + 8] * INV_CAT) + 1e-5f);
        int grow = rowBase + rl;
#pragma unroll
        for (int ni = 0; ni < 8; ni++) {
            int gcol = d0 + n0w + ni * 8 + cq;
            float v0 = g_v[gcol], v1 = g_v[gcol + 1];
            float u0 = g_u[gcol], u1 = g_u[gcol + 1];
            float* a = acc[mi][ni];
            float y0 = gelu_f(fmaf(rs0, a[0] - mu0 * v0, u0));
            float y1 = gelu_f(fmaf(rs0, a[1] - mu0 * v1, u1));
            float y2 = gelu_f(fmaf(rs1, a[2] - mu1 * v0, u0));
            float y3 = gelu_f(fmaf(rs1, a[3] - mu1 * v1, u1));
            *(uint2*)&g_y1[(size_t)grow * 256 + gcol] = make_uint2(pack_hl(y0), pack_hl(y1));
            *(uint2*)&g_y1[(size_t)(grow + 8) * 256 + gcol] = make_uint2(pack_hl(y2), pack_hl(y3));
        }
    }
}

// ---------------- GEMM2: y1 @ W2 + b2, GELU -> out ----------------
__global__ __launch_bounds__(256) void gemm2(const float* __restrict__ b2,
                                             float* __restrict__ out) {
    extern __shared__ char sm[];
    int t = threadIdx.x, l = t & 31, wid = t >> 5;
    int m0w = (wid & 3) * 32, n0w = (wid >> 2) * 64;
    int lr = l & 15, lc = (l & 16) >> 1;
    int rowBase = blockIdx.x * 128, d0 = blockIdx.y * 128;
    int half = t & 1, row = t >> 1;
    int r = rowBase + row;
    uint32_t base = smem_u32(sm);

    float acc[2][8][4];
#pragma unroll
    for (int i = 0; i < 2; i++)
#pragma unroll
        for (int j = 0; j < 8; j++)
#pragma unroll
            for (int k = 0; k < 4; k++) acc[i][j][k] = 0.f;

    uint4 q[4];
    uint32_t hp[8], lp[8];
    const uint32_t* ybase = g_y1 + (size_t)r * 256 + half * 16;

    // prologue
#pragma unroll
    for (int j = 0; j < 4; j++) q[j] = ((const uint4*)ybase)[j];
    cpB(base, 0, g_B2hi + d0, g_B2lo + d0, t);
    CP_COMMIT();
#pragma unroll
    for (int j = 0; j < 4; j++) {
        uint4 v = q[j];
        hp[2 * j]     = (v.x & 0xffffu) | ((v.y & 0xffffu) << 16);
        hp[2 * j + 1] = (v.z & 0xffffu) | ((v.w & 0xffffu) << 16);
        lp[2 * j]     = (v.x >> 16) | (v.y & 0xffff0000u);
        lp[2 * j + 1] = (v.z >> 16) | (v.w & 0xffff0000u);
    }
    stageA_store(sm, 0, row, half, hp, lp);
    CP_WAIT0();
    __syncthreads();

    for (int c = 0; c < NCH2; c++) {
        int s = c & 1, ns = s ^ 1;
        bool more = (c + 1 < NCH2);
        if (more) {
#pragma unroll
            for (int j = 0; j < 4; j++) q[j] = ((const uint4*)(ybase + (c + 1) * 32))[j];
            cpB(base, ns, g_B2hi + (size_t)(c + 1) * 8192 + d0,
                           g_B2lo + (size_t)(c + 1) * 8192 + d0, t);
            CP_COMMIT();
        }
        mma_chunk(acc, base + s * A_ST, base + s * A_ST + 10240,
                       base + B_BASE + s * B_ST, base + B_BASE + s * B_ST + 8704,
                  m0w, n0w, lr, lc);
        if (more) {
#pragma unroll
            for (int j = 0; j < 4; j++) {
                uint4 v = q[j];
                hp[2 * j]     = (v.x & 0xffffu) | ((v.y & 0xffffu) << 16);
                hp[2 * j + 1] = (v.z & 0xffffu) | ((v.w & 0xffffu) << 16);
                lp[2 * j]     = (v.x >> 16) | (v.y & 0xffff0000u);
                lp[2 * j + 1] = (v.z >> 16) | (v.w & 0xffff0000u);
            }
            stageA_store(sm, ns, row, half, hp, lp);
        }
        CP_WAIT0();
        __syncthreads();
    }

    int rq = l >> 2, cq = (l & 3) * 2;
#pragma unroll
    for (int mi = 0; mi < 2; mi++) {
        int rl = m0w + mi * 16 + rq;
        int grow = rowBase + rl;
#pragma unroll
        for (int ni = 0; ni < 8; ni++) {
            int gcol = d0 + n0w + ni * 8 + cq;
            float u0 = b2[gcol], u1 = b2[gcol + 1];
            float* a = acc[mi][ni];
            *(float2*)&out[(size_t)grow * 256 + gcol] =
                make_float2(gelu_f(a[0] + u0), gelu_f(a[1] + u1));
            *(float2*)&out[(size_t)(grow + 8) * 256 + gcol] =
                make_float2(gelu_f(a[2] + u0), gelu_f(a[3] + u1));
        }
    }
}

// ---------------- launch ----------------
extern "C" void kernel_launch(void* const* d_in, const int* in_sizes, int n_in,
                              void* d_out, int out_size) {
    const float* pt    = (const float*)d_in[0];
    const float* sh    = (const float*)d_in[1];
    const float* dyn   = (const float*)d_in[2];
    const float* sem   = (const float*)d_in[3];
    const float* pit   = (const float*)d_in[4];
    const float* rel   = (const float*)d_in[5];
    const float* vis   = (const float*)d_in[6];
    const float* gamma = (const float*)d_in[7];
    const float* beta  = (const float*)d_in[8];
    const float* W1    = (const float*)d_in[9];
    const float* b1    = (const float*)d_in[10];
    const float* W2    = (const float*)d_in[11];
    const float* b2    = (const float*)d_in[12];
    float* out = (float*)d_out;

    cudaFuncSetAttribute(gemm1, cudaFuncAttributeMaxDynamicSharedMemorySize, SMEM_DYN);
    cudaFuncSetAttribute(gemm2, cudaFuncAttributeMaxDynamicSharedMemorySize, SMEM_DYN);

    prep_w1<<<KPAD1, 256>>>(W1, gamma);
    prep_w2<<<256, 256>>>(W2);
    prep_vu<<<1, 256>>>(W1, gamma, beta, b1);
    gemm1<<<dim3(512, 2), 256, SMEM_DYN>>>(pt, sh, dyn, sem, pit, rel, vis);
    gemm2<<<dim3(512, 2), 256, SMEM_DYN>>>(b2, out);
}

// round 7
// speedup vs baseline: 1.6580x; 1.1224x over previous
#include <cuda_runtime.h>
#include <cuda_fp16.h>
#include <cstdint>

#define NCH1 41                 // K1 = 1283 -> 41 chunks of 32
#define NCH2 8                  // K2 = 256  -> 8 chunks of 32
#define KPAD1 1312
#define INV_CAT (1.0f/1283.0f)

// smem layout (bytes, within dynamic smem):
//   A stage s (hi only): s*10240          (128 rows x 40 halves)
//   B stage s: hi at 20480+s*17408, lo at +8704   (32 rows x 136 halves)
#define A_ST   10240
#define B_BASE 20480
#define B_ST   17408
#define SMEM_DYN (B_BASE + 2*B_ST)   // 55296

// ---------------- scratch (no cudaMalloc allowed) ----------------
__device__ __align__(16) __half g_y1[65536u*256];   // fp16 y1
__device__ __align__(16) __half g_B1hi[KPAD1*256];
__device__ __align__(16) __half g_B1lo[KPAD1*256];
__device__ __align__(16) __half g_B2hi[256*256];
__device__ __align__(16) __half g_B2lo[256*256];
__device__ float g_v[256];
__device__ float g_u[256];

// ---------------- helpers ----------------
__device__ __forceinline__ uint32_t smem_u32(const void* p) {
    uint32_t a;
    asm("{ .reg .u64 t; cvta.to.shared.u64 t, %1; cvt.u32.u64 %0, t; }" : "=r"(a) : "l"(p));
    return a;
}
#define CP_A16(dst, src) \
    asm volatile("cp.async.cg.shared.global [%0], [%1], 16;" :: "r"(dst), "l"(src) : "memory")
#define CP_COMMIT() asm volatile("cp.async.commit_group;" ::: "memory")
#define CP_WAIT0()  asm volatile("cp.async.wait_group 0;" ::: "memory")

__device__ __forceinline__ void ldsm_x4(uint32_t* f, uint32_t a) {
    asm volatile("ldmatrix.sync.aligned.m8n8.x4.shared.b16 {%0,%1,%2,%3}, [%4];"
                 : "=r"(f[0]), "=r"(f[1]), "=r"(f[2]), "=r"(f[3]) : "r"(a));
}
__device__ __forceinline__ void ldsm_x4t(uint32_t* f, uint32_t a) {
    asm volatile("ldmatrix.sync.aligned.m8n8.x4.trans.shared.b16 {%0,%1,%2,%3}, [%4];"
                 : "=r"(f[0]), "=r"(f[1]), "=r"(f[2]), "=r"(f[3]) : "r"(a));
}
__device__ __forceinline__ void mma16816(float* c, const uint32_t* a, uint32_t b0, uint32_t b1) {
    asm volatile("mma.sync.aligned.m16n8k16.row.col.f32.f16.f16.f32 "
                 "{%0,%1,%2,%3}, {%4,%5,%6,%7}, {%8,%9}, {%0,%1,%2,%3};"
                 : "+f"(c[0]), "+f"(c[1]), "+f"(c[2]), "+f"(c[3])
                 : "r"(a[0]), "r"(a[1]), "r"(a[2]), "r"(a[3]), "r"(b0), "r"(b1));
}
__device__ __forceinline__ float gelu_f(float x) {
    return 0.5f * x * (1.0f + erff(x * 0.70710678118654752f));
}
__device__ __forceinline__ uint32_t pack_h2(float a, float b) {
    __half2 h = __floats2half2_rn(a, b);
    return *reinterpret_cast<uint32_t*>(&h);
}

// mma core: warptile 64M x 32N, fp16 2-pass (ah*bh + ah*bl).
// A tiles stride 40 halves (hi only), B tiles stride 136 halves.
__device__ __forceinline__ void mma_chunk(float (&acc)[4][4][4],
                                          uint32_t aB,
                                          uint32_t bHiB, uint32_t bLoB,
                                          int m0w, int n0w, int lr, int lc) {
#pragma unroll
    for (int kk = 0; kk < 32; kk += 16) {
        uint32_t ah[4][4], bh[2][4], bl[2][4];
#pragma unroll
        for (int mi = 0; mi < 4; mi++) {
            uint32_t off = (uint32_t)(((m0w + mi * 16 + lr) * 40 + kk + lc) * 2);
            ldsm_x4(ah[mi], aB + off);
        }
#pragma unroll
        for (int np = 0; np < 2; np++) {
            uint32_t boff = (uint32_t)(((kk + lr) * 136 + n0w + np * 16 + lc) * 2);
            ldsm_x4t(bh[np], bHiB + boff);
            ldsm_x4t(bl[np], bLoB + boff);
        }
        // pass 1: ah x bh  (16 MMAs, all-distinct accumulators)
#pragma unroll
        for (int np = 0; np < 2; np++)
#pragma unroll
            for (int mi = 0; mi < 4; mi++) {
                mma16816(acc[mi][np * 2],     ah[mi], bh[np][0], bh[np][1]);
                mma16816(acc[mi][np * 2 + 1], ah[mi], bh[np][2], bh[np][3]);
            }
        // pass 2: ah x bl
#pragma unroll
        for (int np = 0; np < 2; np++)
#pragma unroll
            for (int mi = 0; mi < 4; mi++) {
                mma16816(acc[mi][np * 2],     ah[mi], bl[np][0], bl[np][1]);
                mma16816(acc[mi][np * 2 + 1], ah[mi], bl[np][2], bl[np][3]);
            }
    }
}

// async-copy one B stage (hi+lo) for a chunk; srcHi/srcLo already offset to chunk+d0
__device__ __forceinline__ void cpB(uint32_t smBase, int s,
                                    const __half* srcHi,
                                    const __half* srcLo, int t) {
    int row = t >> 3, colh = (t & 7) * 16;
    uint32_t d = smBase + B_BASE + s * B_ST + (uint32_t)(row * 136 + colh) * 2;
    const char* sH = (const char*)(srcHi + row * 256 + colh);
    const char* sL = (const char*)(srcLo + row * 256 + colh);
    CP_A16(d, sH);            CP_A16(d + 16, sH + 16);
    CP_A16(d + 8704, sL);     CP_A16(d + 8704 + 16, sL + 16);
}

// store 16 hi cols (8 packed half2) into A stage s
__device__ __forceinline__ void stageA_store(char* sm, int s, int row, int half,
                                             const uint32_t* hp) {
    char* da = sm + s * A_ST + (uint32_t)(row * 80 + half * 32);
    ((uint4*)da)[0] = make_uint4(hp[0], hp[1], hp[2], hp[3]);
    ((uint4*)da)[1] = make_uint4(hp[4], hp[5], hp[6], hp[7]);
}

__device__ __forceinline__ void load_x16(const float* const* seg,
                                         const float* rel, const float* vis,
                                         int r, int c, int half, float* x) {
    int c0 = c * 32 + half * 16;
    if (c0 < 1280) {
        const float* p = seg[c0 >> 8] + (c0 & 255);
#pragma unroll
        for (int j = 0; j < 4; j++) {
            float4 f = ((const float4*)p)[j];
            x[4 * j] = f.x; x[4 * j + 1] = f.y; x[4 * j + 2] = f.z; x[4 * j + 3] = f.w;
        }
    } else {
#pragma unroll
        for (int j = 0; j < 16; j++) {
            int cc = c0 + j;
            x[j] = (cc < 1282) ? rel[(size_t)r * 2 + (cc - 1280)]
                 : (cc == 1282) ? vis[r] : 0.f;
        }
    }
}

// ---------------- prep kernels ----------------
__global__ void prep_w1(const float* __restrict__ W1, const float* __restrict__ gamma) {
    int c = blockIdx.x, d = threadIdx.x;
    float w = (c < 1283) ? W1[(size_t)c * 256 + d] * gamma[c] : 0.0f;
    __half h = __float2half_rn(w);
    __half l = __float2half_rn(w - __half2float(h));
    g_B1hi[(size_t)c * 256 + d] = h;
    g_B1lo[(size_t)c * 256 + d] = l;
}
__global__ void prep_w2(const float* __restrict__ W2) {
    int c = blockIdx.x, d = threadIdx.x;
    float w = W2[(size_t)c * 256 + d];
    __half h = __float2half_rn(w);
    __half l = __float2half_rn(w - __half2float(h));
    g_B2hi[(size_t)c * 256 + d] = h;
    g_B2lo[(size_t)c * 256 + d] = l;
}
__global__ void prep_vu(const float* __restrict__ W1, const float* __restrict__ gamma,
                        const float* __restrict__ beta, const float* __restrict__ b1) {
    int d = threadIdx.x;
    float v = 0.f, u = 0.f;
    for (int c = 0; c < 1283; c++) {
        float w = W1[(size_t)c * 256 + d];
        v += gamma[c] * w;
        u += beta[c] * w;
    }
    g_v[d] = v;
    g_u[d] = u + b1[d];
}

// ---------------- GEMM1: raw concat-x @ W1g, LN-folded epilogue + GELU -> g_y1 ----------------
__global__ __launch_bounds__(256) void gemm1(
    const float* __restrict__ pt, const float* __restrict__ sh,
    const float* __restrict__ dyn, const float* __restrict__ sem,
    const float* __restrict__ pit, const float* __restrict__ rel,
    const float* __restrict__ vis) {
    extern __shared__ char sm[];
    __shared__ float s_sum[128], s_ss[128];

    int t = threadIdx.x, l = t & 31, wid = t >> 5;
    int m0w = (wid >> 2) * 64, n0w = (wid & 3) * 32;
    int lr = l & 15, lc = (l & 16) >> 1;
    int rowBase = blockIdx.x * 128, d0 = blockIdx.y * 128;
    int half = t & 1, row = t >> 1;
    int r = rowBase + row;
    int b_ = r >> 14, m_ = (r >> 6) & 255, h_ = r & 63;
    const float* seg[5] = { pt + (size_t)((b_ << 8) + m_) * 256,
                            sh + (size_t)((b_ << 6) + h_) * 256,
                            dyn + (size_t)r * 256,
                            sem + (size_t)r * 256,
                            pit + (size_t)r * 256 };
    uint32_t base = smem_u32(sm);

    float acc[4][4][4];
#pragma unroll
    for (int i = 0; i < 4; i++)
#pragma unroll
        for (int j = 0; j < 4; j++)
#pragma unroll
            for (int k = 0; k < 4; k++) acc[i][j][k] = 0.f;
    float sum = 0.f, ss = 0.f;

    float x[16];
    uint32_t hp[8];

    // ---- prologue: stage chunk 0 ----
    load_x16(seg, rel, vis, r, 0, half, x);
    cpB(base, 0, g_B1hi + d0, g_B1lo + d0, t);
    CP_COMMIT();
#pragma unroll
    for (int j = 0; j < 8; j++) {
        float a = x[2 * j], b = x[2 * j + 1];
        sum += a + b; ss = fmaf(a, a, ss); ss = fmaf(b, b, ss);
        hp[j] = pack_h2(a, b);
    }
    stageA_store(sm, 0, row, half, hp);
    CP_WAIT0();
    __syncthreads();

    for (int c = 0; c < NCH1; c++) {
        int s = c & 1, ns = s ^ 1;
        bool more = (c + 1 < NCH1);
        if (more) {
            load_x16(seg, rel, vis, r, c + 1, half, x);   // LDG in flight over the MMAs
            cpB(base, ns, g_B1hi + (size_t)(c + 1) * 8192 + d0,
                           g_B1lo + (size_t)(c + 1) * 8192 + d0, t);
            CP_COMMIT();
        }
        mma_chunk(acc, base + s * A_ST,
                       base + B_BASE + s * B_ST, base + B_BASE + s * B_ST + 8704,
                  m0w, n0w, lr, lc);
        if (more) {
#pragma unroll
            for (int j = 0; j < 8; j++) {
                float a = x[2 * j], b = x[2 * j + 1];
                sum += a + b; ss = fmaf(a, a, ss); ss = fmaf(b, b, ss);
                hp[j] = pack_h2(a, b);
            }
            stageA_store(sm, ns, row, half, hp);
        }
        CP_WAIT0();
        __syncthreads();
    }

    // ---- row stats ----
    sum += __shfl_xor_sync(0xffffffffu, sum, 1);
    ss  += __shfl_xor_sync(0xffffffffu, ss, 1);
    if (!half) { s_sum[row] = sum; s_ss[row] = ss; }
    __syncthreads();

    // ---- epilogue: LN correction + GELU -> fp16 y1 ----
    int rq = l >> 2, cq = (l & 3) * 2;
#pragma unroll
    for (int mi = 0; mi < 4; mi++) {
        int rl = m0w + mi * 16 + rq;
        float mu0 = s_sum[rl] * INV_CAT;
        float rs0 = rsqrtf(fmaf(-mu0, mu0, s_ss[rl] * INV_CAT) + 1e-5f);
        float mu1 = s_sum[rl + 8] * INV_CAT;
        float rs1 = rsqrtf(fmaf(-mu1, mu1, s_ss[rl + 8] * INV_CAT) + 1e-5f);
        int grow = rowBase + rl;
#pragma unroll
        for (int ni = 0; ni < 4; ni++) {
            int gcol = d0 + n0w + ni * 8 + cq;
            float v0 = g_v[gcol], v1 = g_v[gcol + 1];
            float u0 = g_u[gcol], u1 = g_u[gcol + 1];
            float* a = acc[mi][ni];
            float y0 = gelu_f(fmaf(rs0, a[0] - mu0 * v0, u0));
            float y1 = gelu_f(fmaf(rs0, a[1] - mu0 * v1, u1));
            float y2 = gelu_f(fmaf(rs1, a[2] - mu1 * v0, u0));
            float y3 = gelu_f(fmaf(rs1, a[3] - mu1 * v1, u1));
            *(uint32_t*)&g_y1[(size_t)grow * 256 + gcol] = pack_h2(y0, y1);
            *(uint32_t*)&g_y1[(size_t)(grow + 8) * 256 + gcol] = pack_h2(y2, y3);
        }
    }
}

// ---------------- GEMM2: y1 @ W2 + b2, GELU -> out ----------------
__global__ __launch_bounds__(256) void gemm2(const float* __restrict__ b2,
                                             float* __restrict__ out) {
    extern __shared__ char sm[];
    int t = threadIdx.x, l = t & 31, wid = t >> 5;
    int m0w = (wid >> 2) * 64, n0w = (wid & 3) * 32;
    int lr = l & 15, lc = (l & 16) >> 1;
    int rowBase = blockIdx.x * 128, d0 = blockIdx.y * 128;
    int half = t & 1, row = t >> 1;
    int r = rowBase + row;
    uint32_t base = smem_u32(sm);

    float acc[4][4][4];
#pragma unroll
    for (int i = 0; i < 4; i++)
#pragma unroll
        for (int j = 0; j < 4; j++)
#pragma unroll
            for (int k = 0; k < 4; k++) acc[i][j][k] = 0.f;

    const char* ybase = (const char*)(g_y1 + (size_t)r * 256 + half * 16);
    uint32_t adst = base + (uint32_t)(row * 80 + half * 32);

    // prologue: stage chunk 0 (A via cp.async too)
    CP_A16(adst, ybase);  CP_A16(adst + 16, ybase + 16);
    cpB(base, 0, g_B2hi + d0, g_B2lo + d0, t);
    CP_COMMIT();
    CP_WAIT0();
    __syncthreads();

    for (int c = 0; c < NCH2; c++) {
        int s = c & 1, ns = s ^ 1;
        bool more = (c + 1 < NCH2);
        if (more) {
            const char* ysrc = ybase + (size_t)(c + 1) * 64;
            uint32_t ad = adst + ns * A_ST;
            CP_A16(ad, ysrc);  CP_A16(ad + 16, ysrc + 16);
            cpB(base, ns, g_B2hi + (size_t)(c + 1) * 8192 + d0,
                           g_B2lo + (size_t)(c + 1) * 8192 + d0, t);
            CP_COMMIT();
        }
        mma_chunk(acc, base + s * A_ST,
                       base + B_BASE + s * B_ST, base + B_BASE + s * B_ST + 8704,
                  m0w, n0w, lr, lc);
        CP_WAIT0();
        __syncthreads();
    }

    int rq = l >> 2, cq = (l & 3) * 2;
#pragma unroll
    for (int mi = 0; mi < 4; mi++) {
        int rl = m0w + mi * 16 + rq;
        int grow = rowBase + rl;
#pragma unroll
        for (int ni = 0; ni < 4; ni++) {
            int gcol = d0 + n0w + ni * 8 + cq;
            float u0 = b2[gcol], u1 = b2[gcol + 1];
            float* a = acc[mi][ni];
            *(float2*)&out[(size_t)grow * 256 + gcol] =
                make_float2(gelu_f(a[0] + u0), gelu_f(a[1] + u1));
            *(float2*)&out[(size_t)(grow + 8) * 256 + gcol] =
                make_float2(gelu_f(a[2] + u0), gelu_f(a[3] + u1));
        }
    }
}

// ---------------- launch ----------------
extern "C" void kernel_launch(void* const* d_in, const int* in_sizes, int n_in,
                              void* d_out, int out_size) {
    const float* pt    = (const float*)d_in[0];
    const float* sh    = (const float*)d_in[1];
    const float* dyn   = (const float*)d_in[2];
    const float* sem   = (const float*)d_in[3];
    const float* pit   = (const float*)d_in[4];
    const float* rel   = (const float*)d_in[5];
    const float* vis   = (const float*)d_in[6];
    const float* gamma = (const float*)d_in[7];
    const float* beta  = (const float*)d_in[8];
    const float* W1    = (const float*)d_in[9];
    const float* b1    = (const float*)d_in[10];
    const float* W2    = (const float*)d_in[11];
    const float* b2    = (const float*)d_in[12];
    float* out = (float*)d_out;

    cudaFuncSetAttribute(gemm1, cudaFuncAttributeMaxDynamicSharedMemorySize, SMEM_DYN);
    cudaFuncSetAttribute(gemm2, cudaFuncAttributeMaxDynamicSharedMemorySize, SMEM_DYN);

    prep_w1<<<KPAD1, 256>>>(W1, gamma);
    prep_w2<<<256, 256>>>(W2);
    prep_vu<<<1, 256>>>(W1, gamma, beta, b1);
    gemm1<<<dim3(512, 2), 256, SMEM_DYN>>>(pt, sh, dyn, sem, pit, rel, vis);
    gemm2<<<dim3(512, 2), 256, SMEM_DYN>>>(b2, out);
}

// round 8
// speedup vs baseline: 1.9332x; 1.1660x over previous
#include <cuda_runtime.h>
#include <cuda_fp16.h>
#include <cstdint>

#define NCH1 41                 // K1 = 1283 -> 41 chunks of 32
#define NCH2 8                  // K2 = 256  -> 8 chunks of 32
#define KPAD1 1312
#define INV_CAT (1.0f/1283.0f)

// smem layout (bytes, within dynamic smem):
//   A stage s (hi only): s*10240          (128 rows x 40 halves)
//   B stage s: hi at 20480+s*17408, lo at +8704   (32 rows x 136 halves)
#define A_ST   10240
#define B_BASE 20480
#define B_ST   17408
#define SMEM_DYN (B_BASE + 2*B_ST)   // 55296

// ---------------- scratch (no cudaMalloc allowed) ----------------
__device__ __align__(16) __half g_y1[65536u*256];   // fp16 y1
__device__ __align__(16) __half g_B1hi[KPAD1*256];
__device__ __align__(16) __half g_B1lo[KPAD1*256];
__device__ __align__(16) __half g_B2hi[256*256];
__device__ __align__(16) __half g_B2lo[256*256];
__device__ float g_v[256];
__device__ float g_u[256];

// ---------------- helpers ----------------
__device__ __forceinline__ uint32_t smem_u32(const void* p) {
    uint32_t a;
    asm("{ .reg .u64 t; cvta.to.shared.u64 t, %1; cvt.u32.u64 %0, t; }" : "=r"(a) : "l"(p));
    return a;
}
#define CP_A16(dst, src) \
    asm volatile("cp.async.cg.shared.global [%0], [%1], 16;" :: "r"(dst), "l"(src) : "memory")
#define CP_COMMIT() asm volatile("cp.async.commit_group;" ::: "memory")
#define CP_WAIT0()  asm volatile("cp.async.wait_group 0;" ::: "memory")

__device__ __forceinline__ void ldsm_x4(uint32_t* f, uint32_t a) {
    asm volatile("ldmatrix.sync.aligned.m8n8.x4.shared.b16 {%0,%1,%2,%3}, [%4];"
                 : "=r"(f[0]), "=r"(f[1]), "=r"(f[2]), "=r"(f[3]) : "r"(a));
}
__device__ __forceinline__ void ldsm_x4t(uint32_t* f, uint32_t a) {
    asm volatile("ldmatrix.sync.aligned.m8n8.x4.trans.shared.b16 {%0,%1,%2,%3}, [%4];"
                 : "=r"(f[0]), "=r"(f[1]), "=r"(f[2]), "=r"(f[3]) : "r"(a));
}
__device__ __forceinline__ void mma16816(float* c, const uint32_t* a, uint32_t b0, uint32_t b1) {
    asm volatile("mma.sync.aligned.m16n8k16.row.col.f32.f16.f16.f32 "
                 "{%0,%1,%2,%3}, {%4,%5,%6,%7}, {%8,%9}, {%0,%1,%2,%3};"
                 : "+f"(c[0]), "+f"(c[1]), "+f"(c[2]), "+f"(c[3])
                 : "r"(a[0]), "r"(a[1]), "r"(a[2]), "r"(a[3]), "r"(b0), "r"(b1));
}
__device__ __forceinline__ float gelu_f(float x) {
    return 0.5f * x * (1.0f + erff(x * 0.70710678118654752f));
}
__device__ __forceinline__ uint32_t pack_h2(float a, float b) {
    __half2 h = __floats2half2_rn(a, b);
    return *reinterpret_cast<uint32_t*>(&h);
}

// mma core: warptile 64M x 32N, fp16 2-pass (ah*bh + ah*bl).
// A tiles stride 40 halves (hi only), B tiles stride 136 halves.
__device__ __forceinline__ void mma_chunk(float (&acc)[4][4][4],
                                          uint32_t aB,
                                          uint32_t bHiB, uint32_t bLoB,
                                          int m0w, int n0w, int lr, int lc) {
#pragma unroll
    for (int kk = 0; kk < 32; kk += 16) {
        uint32_t ah[4][4], bh[2][4], bl[2][4];
#pragma unroll
        for (int mi = 0; mi < 4; mi++) {
            uint32_t off = (uint32_t)(((m0w + mi * 16 + lr) * 40 + kk + lc) * 2);
            ldsm_x4(ah[mi], aB + off);
        }
#pragma unroll
        for (int np = 0; np < 2; np++) {
            uint32_t boff = (uint32_t)(((kk + lr) * 136 + n0w + np * 16 + lc) * 2);
            ldsm_x4t(bh[np], bHiB + boff);
            ldsm_x4t(bl[np], bLoB + boff);
        }
        // pass 1: ah x bh  (16 MMAs, all-distinct accumulators)
#pragma unroll
        for (int np = 0; np < 2; np++)
#pragma unroll
            for (int mi = 0; mi < 4; mi++) {
                mma16816(acc[mi][np * 2],     ah[mi], bh[np][0], bh[np][1]);
                mma16816(acc[mi][np * 2 + 1], ah[mi], bh[np][2], bh[np][3]);
            }
        // pass 2: ah x bl
#pragma unroll
        for (int np = 0; np < 2; np++)
#pragma unroll
            for (int mi = 0; mi < 4; mi++) {
                mma16816(acc[mi][np * 2],     ah[mi], bl[np][0], bl[np][1]);
                mma16816(acc[mi][np * 2 + 1], ah[mi], bl[np][2], bl[np][3]);
            }
    }
}

// async-copy one B stage (hi+lo) for a chunk; srcHi/srcLo already offset to chunk+d0
__device__ __forceinline__ void cpB(uint32_t smBase, int s,
                                    const __half* srcHi,
                                    const __half* srcLo, int t) {
    int row = t >> 3, colh = (t & 7) * 16;
    uint32_t d = smBase + B_BASE + s * B_ST + (uint32_t)(row * 136 + colh) * 2;
    const char* sH = (const char*)(srcHi + row * 256 + colh);
    const char* sL = (const char*)(srcLo + row * 256 + colh);
    CP_A16(d, sH);            CP_A16(d + 16, sH + 16);
    CP_A16(d + 8704, sL);     CP_A16(d + 8704 + 16, sL + 16);
}

// store 16 hi cols (8 packed half2) into A stage s
__device__ __forceinline__ void stageA_store(char* sm, int s, int row, int half,
                                             const uint32_t* hp) {
    char* da = sm + s * A_ST + (uint32_t)(row * 80 + half * 32);
    ((uint4*)da)[0] = make_uint4(hp[0], hp[1], hp[2], hp[3]);
    ((uint4*)da)[1] = make_uint4(hp[4], hp[5], hp[6], hp[7]);
}

__device__ __forceinline__ void load_x16(const float* const* seg,
                                         const float* rel, const float* vis,
                                         int r, int c, int half, float* x) {
    int c0 = c * 32 + half * 16;
    if (c0 < 1280) {
        const float* p = seg[c0 >> 8] + (c0 & 255);
#pragma unroll
        for (int j = 0; j < 4; j++) {
            float4 f = ((const float4*)p)[j];
            x[4 * j] = f.x; x[4 * j + 1] = f.y; x[4 * j + 2] = f.z; x[4 * j + 3] = f.w;
        }
    } else {
#pragma unroll
        for (int j = 0; j < 16; j++) {
            int cc = c0 + j;
            x[j] = (cc < 1282) ? rel[(size_t)r * 2 + (cc - 1280)]
                 : (cc == 1282) ? vis[r] : 0.f;
        }
    }
}

// ---------------- prep kernels ----------------
__global__ void prep_w1(const float* __restrict__ W1, const float* __restrict__ gamma) {
    int c = blockIdx.x, d = threadIdx.x;
    float w = (c < 1283) ? W1[(size_t)c * 256 + d] * gamma[c] : 0.0f;
    __half h = __float2half_rn(w);
    __half l = __float2half_rn(w - __half2float(h));
    g_B1hi[(size_t)c * 256 + d] = h;
    g_B1lo[(size_t)c * 256 + d] = l;
}
__global__ void prep_w2(const float* __restrict__ W2) {
    int c = blockIdx.x, d = threadIdx.x;
    float w = W2[(size_t)c * 256 + d];
    __half h = __float2half_rn(w);
    __half l = __float2half_rn(w - __half2float(h));
    g_B2hi[(size_t)c * 256 + d] = h;
    g_B2lo[(size_t)c * 256 + d] = l;
}
__global__ void prep_vu(const float* __restrict__ W1, const float* __restrict__ gamma,
                        const float* __restrict__ beta, const float* __restrict__ b1) {
    int d = threadIdx.x;
    float v = 0.f, u = 0.f;
    for (int c = 0; c < 1283; c++) {
        float w = W1[(size_t)c * 256 + d];
        v += gamma[c] * w;
        u += beta[c] * w;
    }
    g_v[d] = v;
    g_u[d] = u + b1[d];
}

// ---------------- GEMM1: raw concat-x @ W1g, LN-folded epilogue + GELU -> g_y1 ----------------
__global__ __launch_bounds__(256, 2) void gemm1(
    const float* __restrict__ pt, const float* __restrict__ sh,
    const float* __restrict__ dyn, const float* __restrict__ sem,
    const float* __restrict__ pit, const float* __restrict__ rel,
    const float* __restrict__ vis) {
    extern __shared__ char sm[];
    __shared__ float s_sum[128], s_ss[128];

    int t = threadIdx.x, l = t & 31, wid = t >> 5;
    int m0w = (wid >> 2) * 64, n0w = (wid & 3) * 32;
    int lr = l & 15, lc = (l & 16) >> 1;
    int rowBase = blockIdx.x * 128, d0 = blockIdx.y * 128;
    int half = t & 1, row = t >> 1;
    int r = rowBase + row;
    int b_ = r >> 14, m_ = (r >> 6) & 255, h_ = r & 63;
    const float* seg[5] = { pt + (size_t)((b_ << 8) + m_) * 256,
                            sh + (size_t)((b_ << 6) + h_) * 256,
                            dyn + (size_t)r * 256,
                            sem + (size_t)r * 256,
                            pit + (size_t)r * 256 };
    uint32_t base = smem_u32(sm);

    float acc[4][4][4];
#pragma unroll
    for (int i = 0; i < 4; i++)
#pragma unroll
        for (int j = 0; j < 4; j++)
#pragma unroll
            for (int k = 0; k < 4; k++) acc[i][j][k] = 0.f;
    float sum = 0.f, ss = 0.f;

    float x[16];
    uint32_t hp[8];

    // ---- prologue: stage chunk 0 ----
    load_x16(seg, rel, vis, r, 0, half, x);
    cpB(base, 0, g_B1hi + d0, g_B1lo + d0, t);
    CP_COMMIT();
#pragma unroll
    for (int j = 0; j < 8; j++) {
        float a = x[2 * j], b = x[2 * j + 1];
        sum += a + b; ss = fmaf(a, a, ss); ss = fmaf(b, b, ss);
        hp[j] = pack_h2(a, b);
    }
    stageA_store(sm, 0, row, half, hp);
    CP_WAIT0();
    __syncthreads();

    for (int c = 0; c < NCH1; c++) {
        int s = c & 1, ns = s ^ 1;
        bool more = (c + 1 < NCH1);
        if (more) {
            load_x16(seg, rel, vis, r, c + 1, half, x);   // LDG in flight over the MMAs
            cpB(base, ns, g_B1hi + (size_t)(c + 1) * 8192 + d0,
                           g_B1lo + (size_t)(c + 1) * 8192 + d0, t);
            CP_COMMIT();
        }
        mma_chunk(acc, base + s * A_ST,
                       base + B_BASE + s * B_ST, base + B_BASE + s * B_ST + 8704,
                  m0w, n0w, lr, lc);
        if (more) {
#pragma unroll
            for (int j = 0; j < 8; j++) {
                float a = x[2 * j], b = x[2 * j + 1];
                sum += a + b; ss = fmaf(a, a, ss); ss = fmaf(b, b, ss);
                hp[j] = pack_h2(a, b);
            }
            stageA_store(sm, ns, row, half, hp);
        }
        CP_WAIT0();
        __syncthreads();
    }

    // ---- row stats ----
    sum += __shfl_xor_sync(0xffffffffu, sum, 1);
    ss  += __shfl_xor_sync(0xffffffffu, ss, 1);
    if (!half) { s_sum[row] = sum; s_ss[row] = ss; }
    __syncthreads();

    // ---- epilogue: LN correction + GELU -> fp16 y1 ----
    int rq = l >> 2, cq = (l & 3) * 2;
#pragma unroll
    for (int mi = 0; mi < 4; mi++) {
        int rl = m0w + mi * 16 + rq;
        float mu0 = s_sum[rl] * INV_CAT;
        float rs0 = rsqrtf(fmaf(-mu0, mu0, s_ss[rl] * INV_CAT) + 1e-5f);
        float mu1 = s_sum[rl + 8] * INV_CAT;
        float rs1 = rsqrtf(fmaf(-mu1, mu1, s_ss[rl + 8] * INV_CAT) + 1e-5f);
        int grow = rowBase + rl;
#pragma unroll
        for (int ni = 0; ni < 4; ni++) {
            int gcol = d0 + n0w + ni * 8 + cq;
            float v0 = g_v[gcol], v1 = g_v[gcol + 1];
            float u0 = g_u[gcol], u1 = g_u[gcol + 1];
            float* a = acc[mi][ni];
            float y0 = gelu_f(fmaf(rs0, a[0] - mu0 * v0, u0));
            float y1 = gelu_f(fmaf(rs0, a[1] - mu0 * v1, u1));
            float y2 = gelu_f(fmaf(rs1, a[2] - mu1 * v0, u0));
            float y3 = gelu_f(fmaf(rs1, a[3] - mu1 * v1, u1));
            *(uint32_t*)&g_y1[(size_t)grow * 256 + gcol] = pack_h2(y0, y1);
            *(uint32_t*)&g_y1[(size_t)(grow + 8) * 256 + gcol] = pack_h2(y2, y3);
        }
    }
}

// ---------------- GEMM2: y1 @ W2 + b2, GELU -> out ----------------
__global__ __launch_bounds__(256, 2) void gemm2(const float* __restrict__ b2,
                                                float* __restrict__ out) {
    extern __shared__ char sm[];
    int t = threadIdx.x, l = t & 31, wid = t >> 5;
    int m0w = (wid >> 2) * 64, n0w = (wid & 3) * 32;
    int lr = l & 15, lc = (l & 16) >> 1;
    int rowBase = blockIdx.x * 128, d0 = blockIdx.y * 128;
    int half = t & 1, row = t >> 1;
    int r = rowBase + row;
    uint32_t base = smem_u32(sm);

    float acc[4][4][4];
#pragma unroll
    for (int i = 0; i < 4; i++)
#pragma unroll
        for (int j = 0; j < 4; j++)
#pragma unroll
            for (int k = 0; k < 4; k++) acc[i][j][k] = 0.f;

    const char* ybase = (const char*)(g_y1 + (size_t)r * 256 + half * 16);
    uint32_t adst = base + (uint32_t)(row * 80 + half * 32);

    // prologue: stage chunk 0 (A via cp.async too)
    CP_A16(adst, ybase);  CP_A16(adst + 16, ybase + 16);
    cpB(base, 0, g_B2hi + d0, g_B2lo + d0, t);
    CP_COMMIT();
    CP_WAIT0();
    __syncthreads();

    for (int c = 0; c < NCH2; c++) {
        int s = c & 1, ns = s ^ 1;
        bool more = (c + 1 < NCH2);
        if (more) {
            const char* ysrc = ybase + (size_t)(c + 1) * 64;
            uint32_t ad = adst + ns * A_ST;
            CP_A16(ad, ysrc);  CP_A16(ad + 16, ysrc + 16);
            cpB(base, ns, g_B2hi + (size_t)(c + 1) * 8192 + d0,
                           g_B2lo + (size_t)(c + 1) * 8192 + d0, t);
            CP_COMMIT();
        }
        mma_chunk(acc, base + s * A_ST,
                       base + B_BASE + s * B_ST, base + B_BASE + s * B_ST + 8704,
                  m0w, n0w, lr, lc);
        CP_WAIT0();
        __syncthreads();
    }

    int rq = l >> 2, cq = (l & 3) * 2;
#pragma unroll
    for (int mi = 0; mi < 4; mi++) {
        int rl = m0w + mi * 16 + rq;
        int grow = rowBase + rl;
#pragma unroll
        for (int ni = 0; ni < 4; ni++) {
            int gcol = d0 + n0w + ni * 8 + cq;
            float u0 = b2[gcol], u1 = b2[gcol + 1];
            float* a = acc[mi][ni];
            *(float2*)&out[(size_t)grow * 256 + gcol] =
                make_float2(gelu_f(a[0] + u0), gelu_f(a[1] + u1));
            *(float2*)&out[(size_t)(grow + 8) * 256 + gcol] =
                make_float2(gelu_f(a[2] + u0), gelu_f(a[3] + u1));
        }
    }
}

// ---------------- launch ----------------
extern "C" void kernel_launch(void* const* d_in, const int* in_sizes, int n_in,
                              void* d_out, int out_size) {
    const float* pt    = (const float*)d_in[0];
    const float* sh    = (const float*)d_in[1];
    const float* dyn   = (const float*)d_in[2];
    const float* sem   = (const float*)d_in[3];
    const float* pit   = (const float*)d_in[4];
    const float* rel   = (const float*)d_in[5];
    const float* vis   = (const float*)d_in[6];
    const float* gamma = (const float*)d_in[7];
    const float* beta  = (const float*)d_in[8];
    const float* W1    = (const float*)d_in[9];
    const float* b1    = (const float*)d_in[10];
    const float* W2    = (const float*)d_in[11];
    const float* b2    = (const float*)d_in[12];
    float* out = (float*)d_out;

    cudaFuncSetAttribute(gemm1, cudaFuncAttributeMaxDynamicSharedMemorySize, SMEM_DYN);
    cudaFuncSetAttribute(gemm2, cudaFuncAttributeMaxDynamicSharedMemorySize, SMEM_DYN);

    prep_w1<<<KPAD1, 256>>>(W1, gamma);
    prep_w2<<<256, 256>>>(W2);
    prep_vu<<<1, 256>>>(W1, gamma, beta, b1);
    gemm1<<<dim3(512, 2), 256, SMEM_DYN>>>(pt, sh, dyn, sem, pit, rel, vis);
    gemm2<<<dim3(512, 2), 256, SMEM_DYN>>>(b2, out);
}

// round 9
// speedup vs baseline: 2.3921x; 1.2374x over previous
#include <cuda_runtime.h>
#include <cuda_fp16.h>
#include <cstdint>

#define NCH1 21                 // K1 = 1283 -> 21 chunks of 64
#define NCH2 4                  // K2 = 256  -> 4 chunks of 64
#define KPAD1 1344
#define INV_CAT (1.0f/1283.0f)

// smem (bytes): A stage s at s*18432 (128 rows x 72 halves);
//               B stage s at 36864 + s*17408 (64 rows x 136 halves)
#define A_ST   18432
#define B_BASE 36864
#define B_ST   17408
#define SMEM_DYN (B_BASE + 2*B_ST)   // 71680

// ---------------- scratch (no cudaMalloc allowed) ----------------
__device__ __align__(16) __half g_y1[65536u*256];
__device__ __align__(16) __half g_B1h[KPAD1*256];
__device__ __align__(16) __half g_B2h[256*256];
__device__ float g_v[256];
__device__ float g_u[256];
__device__ float g_part[16*512];

// ---------------- helpers ----------------
__device__ __forceinline__ uint32_t smem_u32(const void* p) {
    uint32_t a;
    asm("{ .reg .u64 t; cvta.to.shared.u64 t, %1; cvt.u32.u64 %0, t; }" : "=r"(a) : "l"(p));
    return a;
}
#define CP_A16(dst, src) \
    asm volatile("cp.async.cg.shared.global [%0], [%1], 16;" :: "r"(dst), "l"(src) : "memory")
#define CP_COMMIT() asm volatile("cp.async.commit_group;" ::: "memory")
#define CP_WAIT0()  asm volatile("cp.async.wait_group 0;" ::: "memory")

__device__ __forceinline__ void ldsm_x4(uint32_t* f, uint32_t a) {
    asm volatile("ldmatrix.sync.aligned.m8n8.x4.shared.b16 {%0,%1,%2,%3}, [%4];"
                 : "=r"(f[0]), "=r"(f[1]), "=r"(f[2]), "=r"(f[3]) : "r"(a));
}
__device__ __forceinline__ void ldsm_x4t(uint32_t* f, uint32_t a) {
    asm volatile("ldmatrix.sync.aligned.m8n8.x4.trans.shared.b16 {%0,%1,%2,%3}, [%4];"
                 : "=r"(f[0]), "=r"(f[1]), "=r"(f[2]), "=r"(f[3]) : "r"(a));
}
__device__ __forceinline__ void mma16816(float* c, const uint32_t* a, uint32_t b0, uint32_t b1) {
    asm volatile("mma.sync.aligned.m16n8k16.row.col.f32.f16.f16.f32 "
                 "{%0,%1,%2,%3}, {%4,%5,%6,%7}, {%8,%9}, {%0,%1,%2,%3};"
                 : "+f"(c[0]), "+f"(c[1]), "+f"(c[2]), "+f"(c[3])
                 : "r"(a[0]), "r"(a[1]), "r"(a[2]), "r"(a[3]), "r"(b0), "r"(b1));
}
__device__ __forceinline__ float gelu_f(float x) {
    return 0.5f * x * (1.0f + erff(x * 0.70710678118654752f));
}
__device__ __forceinline__ uint32_t pack_h2(float a, float b) {
    __half2 h = __floats2half2_rn(a, b);
    return *reinterpret_cast<uint32_t*>(&h);
}

// one k-step (K=16): 4 A-ldsm + 2 B-ldsm + 16 MMAs (warptile 64M x 32N)
__device__ __forceinline__ void mma_kstep(float (&acc)[4][4][4],
                                          uint32_t aB, uint32_t bB, int kk,
                                          int m0w, int n0w, int lr, int lc) {
    uint32_t ah[4][4], b[2][4];
#pragma unroll
    for (int mi = 0; mi < 4; mi++) {
        uint32_t off = (uint32_t)(((m0w + mi * 16 + lr) * 72 + kk + lc) * 2);
        ldsm_x4(ah[mi], aB + off);
    }
#pragma unroll
    for (int np = 0; np < 2; np++) {
        uint32_t boff = (uint32_t)(((kk + lr) * 136 + n0w + np * 16 + lc) * 2);
        ldsm_x4t(b[np], bB + boff);
    }
#pragma unroll
    for (int np = 0; np < 2; np++)
#pragma unroll
        for (int mi = 0; mi < 4; mi++) {
            mma16816(acc[mi][np * 2],     ah[mi], b[np][0], b[np][1]);
            mma16816(acc[mi][np * 2 + 1], ah[mi], b[np][2], b[np][3]);
        }
}

// async-copy one 64x128 fp16 B chunk; src pre-offset to chunk row 0 + d0
__device__ __forceinline__ void cpB(uint32_t smBase, int s, const __half* src, int t) {
    int row = t >> 2, colh = (t & 3) * 32;
    uint32_t d = smBase + B_BASE + s * B_ST + (uint32_t)(row * 136 + colh) * 2;
    const char* sp = (const char*)(src + row * 256 + colh);
    CP_A16(d, sp);       CP_A16(d + 16, sp + 16);
    CP_A16(d + 32, sp + 32); CP_A16(d + 48, sp + 48);
}

// load 16 fp32 cols at absolute col c0 for row r
__device__ __forceinline__ void load_x16(const float* const* seg,
                                         const float* rel, const float* vis,
                                         int r, int c0, float* x) {
    if (c0 < 1280) {
        const float* p = seg[c0 >> 8] + (c0 & 255);
#pragma unroll
        for (int j = 0; j < 4; j++) {
            float4 f = ((const float4*)p)[j];
            x[4 * j] = f.x; x[4 * j + 1] = f.y; x[4 * j + 2] = f.z; x[4 * j + 3] = f.w;
        }
    } else {
#pragma unroll
        for (int j = 0; j < 16; j++) x[j] = 0.f;
        if (c0 == 1280) {
            x[0] = rel[(size_t)r * 2];
            x[1] = rel[(size_t)r * 2 + 1];
            x[2] = vis[r];
        }
    }
}

// pack 16 cols -> 8 half2, store into A stage s at (row, half, part)
__device__ __forceinline__ void packA(char* sm, int s, int row, int half, int part,
                                      const float* x, float& sum, float& ss) {
    uint32_t hp[8];
#pragma unroll
    for (int j = 0; j < 8; j++) {
        float a = x[2 * j], b = x[2 * j + 1];
        sum += a + b; ss = fmaf(a, a, ss); ss = fmaf(b, b, ss);
        hp[j] = pack_h2(a, b);
    }
    char* da = sm + s * A_ST + (uint32_t)(row * 144 + half * 64 + part * 32);
    ((uint4*)da)[0] = make_uint4(hp[0], hp[1], hp[2], hp[3]);
    ((uint4*)da)[1] = make_uint4(hp[4], hp[5], hp[6], hp[7]);
}

// ---------------- prep kernels ----------------
__global__ void prep_w1(const float* __restrict__ W1, const float* __restrict__ gamma) {
    int c = blockIdx.x, d = threadIdx.x;
    float w = (c < 1283) ? W1[(size_t)c * 256 + d] * gamma[c] : 0.0f;
    g_B1h[(size_t)c * 256 + d] = __float2half_rn(w);
}
__global__ void prep_w2(const float* __restrict__ W2) {
    int c = blockIdx.x, d = threadIdx.x;
    g_B2h[(size_t)c * 256 + d] = __float2half_rn(W2[(size_t)c * 256 + d]);
}
__global__ void prep_vu_part(const float* __restrict__ W1, const float* __restrict__ gamma,
                             const float* __restrict__ beta) {
    int b = blockIdx.x, d = threadIdx.x;
    int c0 = b * 81, c1 = c0 + 81; if (c1 > 1283) c1 = 1283;
    float v = 0.f, u = 0.f;
    for (int c = c0; c < c1; c++) {
        float w = W1[(size_t)c * 256 + d];
        v += gamma[c] * w;
        u += beta[c] * w;
    }
    g_part[b * 512 + d] = v;
    g_part[b * 512 + 256 + d] = u;
}
__global__ void prep_vu_fin(const float* __restrict__ b1) {
    int d = threadIdx.x;
    float v = 0.f, u = 0.f;
#pragma unroll
    for (int b = 0; b < 16; b++) {
        v += g_part[b * 512 + d];
        u += g_part[b * 512 + 256 + d];
    }
    g_v[d] = v;
    g_u[d] = u + b1[d];
}

// ---------------- GEMM1: raw concat-x @ W1g, LN-folded epilogue + GELU -> g_y1 ----------------
__global__ __launch_bounds__(256, 2) void gemm1(
    const float* __restrict__ pt, const float* __restrict__ sh,
    const float* __restrict__ dyn, const float* __restrict__ sem,
    const float* __restrict__ pit, const float* __restrict__ rel,
    const float* __restrict__ vis) {
    extern __shared__ char sm[];
    __shared__ float s_sum[128], s_ss[128];

    int t = threadIdx.x, l = t & 31, wid = t >> 5;
    int m0w = (wid >> 2) * 64, n0w = (wid & 3) * 32;
    int lr = l & 15, lc = (l & 16) >> 1;
    int d0 = blockIdx.x * 128, rowBase = blockIdx.y * 128;
    int half = t & 1, row = t >> 1;
    int r = rowBase + row;
    int b_ = r >> 14, m_ = (r >> 6) & 255, h_ = r & 63;
    const float* seg[5] = { pt + (size_t)((b_ << 8) + m_) * 256,
                            sh + (size_t)((b_ << 6) + h_) * 256,
                            dyn + (size_t)r * 256,
                            sem + (size_t)r * 256,
                            pit + (size_t)r * 256 };
    uint32_t base = smem_u32(sm);
    int cbase = half * 32;   // this thread's first col within a chunk

    float acc[4][4][4];
#pragma unroll
    for (int i = 0; i < 4; i++)
#pragma unroll
        for (int j = 0; j < 4; j++)
#pragma unroll
            for (int k = 0; k < 4; k++) acc[i][j][k] = 0.f;
    float sum = 0.f, ss = 0.f;
    float xa[16], xb[16];

    // ---- prologue: stage chunk 0 ----
    load_x16(seg, rel, vis, r, cbase, xa);
    load_x16(seg, rel, vis, r, cbase + 16, xb);
    cpB(base, 0, g_B1h + d0, t);
    CP_COMMIT();
    packA(sm, 0, row, half, 0, xa, sum, ss);
    packA(sm, 0, row, half, 1, xb, sum, ss);
    CP_WAIT0();
    __syncthreads();

    for (int c = 0; c < NCH1; c++) {
        int s = c & 1, ns = s ^ 1;
        bool more = (c + 1 < NCH1);
        uint32_t aB = base + s * A_ST, bB = base + B_BASE + s * B_ST;
        if (more) {
            load_x16(seg, rel, vis, r, (c + 1) * 64 + cbase, xa);
            cpB(base, ns, g_B1h + (size_t)(c + 1) * 16384 + d0, t);
            CP_COMMIT();
        }
        mma_kstep(acc, aB, bB, 0, m0w, n0w, lr, lc);
        mma_kstep(acc, aB, bB, 16, m0w, n0w, lr, lc);
        if (more) {
            load_x16(seg, rel, vis, r, (c + 1) * 64 + cbase + 16, xb);
            packA(sm, ns, row, half, 0, xa, sum, ss);
        }
        mma_kstep(acc, aB, bB, 32, m0w, n0w, lr, lc);
        mma_kstep(acc, aB, bB, 48, m0w, n0w, lr, lc);
        if (more) packA(sm, ns, row, half, 1, xb, sum, ss);
        CP_WAIT0();
        __syncthreads();
    }

    // ---- row stats ----
    sum += __shfl_xor_sync(0xffffffffu, sum, 1);
    ss  += __shfl_xor_sync(0xffffffffu, ss, 1);
    if (!half) { s_sum[row] = sum; s_ss[row] = ss; }
    __syncthreads();

    // ---- epilogue: LN correction + GELU -> fp16 y1 ----
    int rq = l >> 2, cq = (l & 3) * 2;
#pragma unroll
    for (int mi = 0; mi < 4; mi++) {
        int rl = m0w + mi * 16 + rq;
        float mu0 = s_sum[rl] * INV_CAT;
        float rs0 = rsqrtf(fmaf(-mu0, mu0, s_ss[rl] * INV_CAT) + 1e-5f);
        float mu1 = s_sum[rl + 8] * INV_CAT;
        float rs1 = rsqrtf(fmaf(-mu1, mu1, s_ss[rl + 8] * INV_CAT) + 1e-5f);
        int grow = rowBase + rl;
#pragma unroll
        for (int ni = 0; ni < 4; ni++) {
            int gcol = d0 + n0w + ni * 8 + cq;
            float v0 = g_v[gcol], v1 = g_v[gcol + 1];
            float u0 = g_u[gcol], u1 = g_u[gcol + 1];
            float* a = acc[mi][ni];
            float y0 = gelu_f(fmaf(rs0, a[0] - mu0 * v0, u0));
            float y1 = gelu_f(fmaf(rs0, a[1] - mu0 * v1, u1));
            float y2 = gelu_f(fmaf(rs1, a[2] - mu1 * v0, u0));
            float y3 = gelu_f(fmaf(rs1, a[3] - mu1 * v1, u1));
            *(uint32_t*)&g_y1[(size_t)grow * 256 + gcol] = pack_h2(y0, y1);
            *(uint32_t*)&g_y1[(size_t)(grow + 8) * 256 + gcol] = pack_h2(y2, y3);
        }
    }
}

// ---------------- GEMM2: y1 @ W2 + b2, GELU -> out ----------------
__global__ __launch_bounds__(256, 2) void gemm2(const float* __restrict__ b2,
                                                float* __restrict__ out) {
    extern __shared__ char sm[];
    int t = threadIdx.x, l = t & 31, wid = t >> 5;
    int m0w = (wid >> 2) * 64, n0w = (wid & 3) * 32;
    int lr = l & 15, lc = (l & 16) >> 1;
    int d0 = blockIdx.x * 128, rowBase = blockIdx.y * 128;
    int half = t & 1, row = t >> 1;
    int r = rowBase + row;
    uint32_t base = smem_u32(sm);

    float acc[4][4][4];
#pragma unroll
    for (int i = 0; i < 4; i++)
#pragma unroll
        for (int j = 0; j < 4; j++)
#pragma unroll
            for (int k = 0; k < 4; k++) acc[i][j][k] = 0.f;

    const char* ybase = (const char*)(g_y1 + (size_t)r * 256 + half * 32);
    uint32_t adst = base + (uint32_t)(row * 144 + half * 64);

    // prologue: stage chunk 0 via cp.async
    CP_A16(adst, ybase);       CP_A16(adst + 16, ybase + 16);
    CP_A16(adst + 32, ybase + 32); CP_A16(adst + 48, ybase + 48);
    cpB(base, 0, g_B2h + d0, t);
    CP_COMMIT();
    CP_WAIT0();
    __syncthreads();

    for (int c = 0; c < NCH2; c++) {
        int s = c & 1, ns = s ^ 1;
        bool more = (c + 1 < NCH2);
        uint32_t aB = base + s * A_ST, bB = base + B_BASE + s * B_ST;
        if (more) {
            const char* ysrc = ybase + (size_t)(c + 1) * 128;
            uint32_t ad = adst + ns * A_ST;
            CP_A16(ad, ysrc);       CP_A16(ad + 16, ysrc + 16);
            CP_A16(ad + 32, ysrc + 32); CP_A16(ad + 48, ysrc + 48);
            cpB(base, ns, g_B2h + (size_t)(c + 1) * 16384 + d0, t);
            CP_COMMIT();
        }
        mma_kstep(acc, aB, bB, 0, m0w, n0w, lr, lc);
        mma_kstep(acc, aB, bB, 16, m0w, n0w, lr, lc);
        mma_kstep(acc, aB, bB, 32, m0w, n0w, lr, lc);
        mma_kstep(acc, aB, bB, 48, m0w, n0w, lr, lc);
        CP_WAIT0();
        __syncthreads();
    }

    int rq = l >> 2, cq = (l & 3) * 2;
#pragma unroll
    for (int mi = 0; mi < 4; mi++) {
        int rl = m0w + mi * 16 + rq;
        int grow = rowBase + rl;
#pragma unroll
        for (int ni = 0; ni < 4; ni++) {
            int gcol = d0 + n0w + ni * 8 + cq;
            float u0 = b2[gcol], u1 = b2[gcol + 1];
            float* a = acc[mi][ni];
            *(float2*)&out[(size_t)grow * 256 + gcol] =
                make_float2(gelu_f(a[0] + u0), gelu_f(a[1] + u1));
            *(float2*)&out[(size_t)(grow + 8) * 256 + gcol] =
                make_float2(gelu_f(a[2] + u0), gelu_f(a[3] + u1));
        }
    }
}

// ---------------- launch ----------------
extern "C" void kernel_launch(void* const* d_in, const int* in_sizes, int n_in,
                              void* d_out, int out_size) {
    const float* pt    = (const float*)d_in[0];
    const float* sh    = (const float*)d_in[1];
    const float* dyn   = (const float*)d_in[2];
    const float* sem   = (const float*)d_in[3];
    const float* pit   = (const float*)d_in[4];
    const float* rel   = (const float*)d_in[5];
    const float* vis   = (const float*)d_in[6];
    const float* gamma = (const float*)d_in[7];
    const float* beta  = (const float*)d_in[8];
    const float* W1    = (const float*)d_in[9];
    const float* b1    = (const float*)d_in[10];
    const float* W2    = (const float*)d_in[11];
    const float* b2    = (const float*)d_in[12];
    float* out = (float*)d_out;

    cudaFuncSetAttribute(gemm1, cudaFuncAttributeMaxDynamicSharedMemorySize, SMEM_DYN);
    cudaFuncSetAttribute(gemm2, cudaFuncAttributeMaxDynamicSharedMemorySize, SMEM_DYN);

    prep_w1<<<KPAD1, 256>>>(W1, gamma);
    prep_w2<<<256, 256>>>(W2);
    prep_vu_part<<<16, 256>>>(W1, gamma, beta);
    prep_vu_fin<<<1, 256>>>(b1);
    gemm1<<<dim3(2, 512), 256, SMEM_DYN>>>(pt, sh, dyn, sem, pit, rel, vis);
    gemm2<<<dim3(2, 512), 256, SMEM_DYN>>>(b2, out);
}